// round 1
// baseline (speedup 1.0000x reference)
#include <cuda_runtime.h>

#define Bn 8
#define Sn 2048
#define En 1024
#define Hn 64
#define Mn (Bn * Sn)

// Scratch for projected Q, K, V (allocation-free: device globals)
__device__ float g_q[Mn * Hn];
__device__ float g_k[Mn * Hn];
__device__ float g_v[Mn * Hn];

// ---------------------------------------------------------------------------
// Kernel 1: fused QKV projection.
// GEMM M=16384, K=1024, N=64, three weight matrices sharing the x tile.
// Block tile 64x64, thread microtile 4x4 per matrix (48 accumulators).
// ---------------------------------------------------------------------------
__global__ __launch_bounds__(256) void qkv_kernel(
    const float* __restrict__ x,
    const float* __restrict__ wq, const float* __restrict__ bq,
    const float* __restrict__ wk, const float* __restrict__ bk,
    const float* __restrict__ wv, const float* __restrict__ bv)
{
    __shared__ float xs[32][64];        // [k][m] transposed x tile
    __shared__ float ws[3][32][64];     // [mtx][k][h]

    const int t  = threadIdx.x;
    const int ty = t >> 4;              // 0..15 -> rows ty*4..ty*4+3
    const int tx = t & 15;              // 0..15 -> cols tx*4..tx*4+3
    const int m0 = blockIdx.x * 64;

    const float* wptr[3] = {wq, wk, wv};

    float acc[3][4][4];
#pragma unroll
    for (int m = 0; m < 3; m++)
#pragma unroll
        for (int i = 0; i < 4; i++)
#pragma unroll
            for (int j = 0; j < 4; j++)
                acc[m][i][j] = 0.0f;

    for (int k0 = 0; k0 < En; k0 += 32) {
        // Load x tile [64 rows][32 k] -> transposed smem xs[k][row]
#pragma unroll
        for (int l = 0; l < 2; l++) {
            int idx = t + l * 256;              // 0..511
            int r   = idx >> 3;                 // row 0..63
            int c4  = idx & 7;                  // float4 within 32 k
            float4 v4 = *(const float4*)(x + (size_t)(m0 + r) * En + k0 + c4 * 4);
            xs[c4 * 4 + 0][r] = v4.x;
            xs[c4 * 4 + 1][r] = v4.y;
            xs[c4 * 4 + 2][r] = v4.z;
            xs[c4 * 4 + 3][r] = v4.w;
        }
        // Load weight tiles [32 k][64 h] for 3 matrices
#pragma unroll
        for (int m = 0; m < 3; m++) {
#pragma unroll
            for (int l = 0; l < 2; l++) {
                int idx = t + l * 256;          // 0..511
                int r   = idx >> 4;             // k-row 0..31
                int c4  = idx & 15;             // float4 within 64 h
                *(float4*)&ws[m][r][c4 * 4] =
                    *(const float4*)(wptr[m] + (size_t)(k0 + r) * Hn + c4 * 4);
            }
        }
        __syncthreads();

#pragma unroll
        for (int kk = 0; kk < 32; kk++) {
            float a[4];
#pragma unroll
            for (int i = 0; i < 4; i++) a[i] = xs[kk][ty * 4 + i];
#pragma unroll
            for (int m = 0; m < 3; m++) {
                float4 b4 = *(float4*)&ws[m][kk][tx * 4];
#pragma unroll
                for (int i = 0; i < 4; i++) {
                    acc[m][i][0] = fmaf(a[i], b4.x, acc[m][i][0]);
                    acc[m][i][1] = fmaf(a[i], b4.y, acc[m][i][1]);
                    acc[m][i][2] = fmaf(a[i], b4.z, acc[m][i][2]);
                    acc[m][i][3] = fmaf(a[i], b4.w, acc[m][i][3]);
                }
            }
        }
        __syncthreads();
    }

    // Epilogue: add bias, store to g_q/g_k/g_v
    float* outp[3] = {g_q, g_k, g_v};
    const float* bptr[3] = {bq, bk, bv};
#pragma unroll
    for (int m = 0; m < 3; m++) {
        float4 bb = *(const float4*)(bptr[m] + tx * 4);
#pragma unroll
        for (int i = 0; i < 4; i++) {
            int row = m0 + ty * 4 + i;
            float4 o;
            o.x = acc[m][i][0] + bb.x;
            o.y = acc[m][i][1] + bb.y;
            o.z = acc[m][i][2] + bb.z;
            o.w = acc[m][i][3] + bb.w;
            *(float4*)(outp[m] + (size_t)row * Hn + tx * 4) = o;
        }
    }
}

// ---------------------------------------------------------------------------
// Kernel 2: causal flash attention, one block per (batch, 64-row q tile).
// 256 threads, 4x4 register microtiles, online softmax via warp shuffles.
// ---------------------------------------------------------------------------
#define KST_LD 68   // padded leading dim (floats), 16B-aligned rows
#define VS_LD  68

__global__ __launch_bounds__(256) void attn_kernel(float* __restrict__ y)
{
    extern __shared__ float sm[];
    float* qs  = sm;                         // [64][64]
    float* kst = qs  + 64 * 64;              // [64 h][KST_LD] transposed K
    float* vs  = kst + 64 * KST_LD;          // [64 k][VS_LD]
    float* ps  = vs  + 64 * VS_LD;           // [64][64] exp'd scores

    const int t  = threadIdx.x;
    const int ty = t >> 4;
    const int tx = t & 15;
    const int b  = blockIdx.y;
    const int qt = blockIdx.x;
    const int q0 = qt * 64;

    const float* Q = g_q + ((size_t)b * Sn + q0) * Hn;

    // Load Q tile, pre-scaled by 1/sqrt(H)=0.125
#pragma unroll
    for (int l = 0; l < 4; l++) {
        int idx = t + l * 256;       // 0..1023
        int r   = idx >> 4;          // 0..63
        int h4  = idx & 15;
        float4 v4 = *(const float4*)(Q + (size_t)r * Hn + h4 * 4);
        v4.x *= 0.125f; v4.y *= 0.125f; v4.z *= 0.125f; v4.w *= 0.125f;
        *(float4*)(qs + r * 64 + h4 * 4) = v4;
    }

    float m_i[4], l_i[4], o[4][4];
#pragma unroll
    for (int i = 0; i < 4; i++) {
        m_i[i] = -1e30f;
        l_i[i] = 0.0f;
#pragma unroll
        for (int j = 0; j < 4; j++) o[i][j] = 0.0f;
    }

    for (int jt = 0; jt <= qt; jt++) {
        const float* K = g_k + ((size_t)b * Sn + jt * 64) * Hn;
        const float* V = g_v + ((size_t)b * Sn + jt * 64) * Hn;

        __syncthreads();   // previous iteration done reading kst/vs/ps (also fences qs on iter 0)
#pragma unroll
        for (int l = 0; l < 4; l++) {
            int idx = t + l * 256;
            int r   = idx >> 4;
            int h4  = idx & 15;
            float4 kv = *(const float4*)(K + (size_t)r * Hn + h4 * 4);
            kst[(h4 * 4 + 0) * KST_LD + r] = kv.x;
            kst[(h4 * 4 + 1) * KST_LD + r] = kv.y;
            kst[(h4 * 4 + 2) * KST_LD + r] = kv.z;
            kst[(h4 * 4 + 3) * KST_LD + r] = kv.w;
            float4 vv = *(const float4*)(V + (size_t)r * Hn + h4 * 4);
            *(float4*)(vs + r * VS_LD + h4 * 4) = vv;
        }
        __syncthreads();

        // S = Q K^T (scaled), 4x4 microtile: rows ty*4.., key-cols tx*4..
        float s[4][4];
#pragma unroll
        for (int i = 0; i < 4; i++)
#pragma unroll
            for (int j = 0; j < 4; j++) s[i][j] = 0.0f;

#pragma unroll 8
        for (int h = 0; h < 64; h++) {
            float a[4];
#pragma unroll
            for (int i = 0; i < 4; i++) a[i] = qs[(ty * 4 + i) * 64 + h];
            float4 b4 = *(float4*)(kst + h * KST_LD + tx * 4);
#pragma unroll
            for (int i = 0; i < 4; i++) {
                s[i][0] = fmaf(a[i], b4.x, s[i][0]);
                s[i][1] = fmaf(a[i], b4.y, s[i][1]);
                s[i][2] = fmaf(a[i], b4.z, s[i][2]);
                s[i][3] = fmaf(a[i], b4.w, s[i][3]);
            }
        }

        // Causal mask on diagonal tile (q0 == jt*64 -> compare local indices)
        if (jt == qt) {
#pragma unroll
            for (int i = 0; i < 4; i++)
#pragma unroll
                for (int j = 0; j < 4; j++)
                    if (tx * 4 + j > ty * 4 + i) s[i][j] = -1e30f;
        }

        // Online softmax per row (reduce over the 16 tx lanes of each 16-lane group)
        float alpha[4];
#pragma unroll
        for (int i = 0; i < 4; i++) {
            float mx = fmaxf(fmaxf(s[i][0], s[i][1]), fmaxf(s[i][2], s[i][3]));
#pragma unroll
            for (int off = 8; off >= 1; off >>= 1)
                mx = fmaxf(mx, __shfl_xor_sync(0xffffffff, mx, off));
            float mnew = fmaxf(m_i[i], mx);
            alpha[i] = __expf(m_i[i] - mnew);
            float rs = 0.0f;
#pragma unroll
            for (int j = 0; j < 4; j++) {
                s[i][j] = __expf(s[i][j] - mnew);
                rs += s[i][j];
            }
#pragma unroll
            for (int off = 8; off >= 1; off >>= 1)
                rs += __shfl_xor_sync(0xffffffff, rs, off);
            l_i[i] = l_i[i] * alpha[i] + rs;
            m_i[i] = mnew;
        }

        // Stage P to smem for the O GEMM
#pragma unroll
        for (int i = 0; i < 4; i++)
            *(float4*)(ps + (ty * 4 + i) * 64 + tx * 4) =
                make_float4(s[i][0], s[i][1], s[i][2], s[i][3]);
        __syncthreads();

        // O = O*alpha + P @ V
#pragma unroll
        for (int i = 0; i < 4; i++)
#pragma unroll
            for (int j = 0; j < 4; j++) o[i][j] *= alpha[i];

#pragma unroll 8
        for (int k = 0; k < 64; k++) {
            float a[4];
#pragma unroll
            for (int i = 0; i < 4; i++) a[i] = ps[(ty * 4 + i) * 64 + k];
            float4 b4 = *(float4*)(vs + k * VS_LD + tx * 4);
#pragma unroll
            for (int i = 0; i < 4; i++) {
                o[i][0] = fmaf(a[i], b4.x, o[i][0]);
                o[i][1] = fmaf(a[i], b4.y, o[i][1]);
                o[i][2] = fmaf(a[i], b4.z, o[i][2]);
                o[i][3] = fmaf(a[i], b4.w, o[i][3]);
            }
        }
    }

    // Normalize and write out
    float* Y = y + ((size_t)b * Sn + q0) * Hn;
#pragma unroll
    for (int i = 0; i < 4; i++) {
        float inv = 1.0f / l_i[i];
        float4 ov;
        ov.x = o[i][0] * inv;
        ov.y = o[i][1] * inv;
        ov.z = o[i][2] * inv;
        ov.w = o[i][3] * inv;
        *(float4*)(Y + (size_t)(ty * 4 + i) * Hn + tx * 4) = ov;
    }
}

// ---------------------------------------------------------------------------
extern "C" void kernel_launch(void* const* d_in, const int* in_sizes, int n_in,
                              void* d_out, int out_size)
{
    const float* x  = (const float*)d_in[0];
    const float* wq = (const float*)d_in[1];
    const float* bq = (const float*)d_in[2];
    const float* wk = (const float*)d_in[3];
    const float* bk = (const float*)d_in[4];
    const float* wv = (const float*)d_in[5];
    const float* bv = (const float*)d_in[6];
    float* y = (float*)d_out;

    qkv_kernel<<<Mn / 64, 256>>>(x, wq, bq, wk, bk, wv, bv);

    const int smem_bytes = (64 * 64 + 64 * KST_LD + 64 * VS_LD + 64 * 64) * sizeof(float);
    cudaFuncSetAttribute(attn_kernel, cudaFuncAttributeMaxDynamicSharedMemorySize, smem_bytes);
    attn_kernel<<<dim3(Sn / 64, Bn), 256, smem_bytes>>>(y);
}

// round 2
// speedup vs baseline: 1.3588x; 1.3588x over previous
#include <cuda_runtime.h>

#define Bn 8
#define Sn 2048
#define En 1024
#define Hn 64
#define Mn (Bn * Sn)

#define QT_N   32        // number of 64-row q tiles per batch
#define CHUNK  4         // key tiles per partial block
#define MAXC   8         // max chunks per q tile (ceil(32/4))

// Scratch for projected Q, K, V (allocation-free: device globals)
__device__ float g_q[Mn * Hn];
__device__ float g_k[Mn * Hn];
__device__ float g_v[Mn * Hn];

// Split-K partial results: unnormalized O, row max m, row sum l
__device__ float g_po[(size_t)Bn * QT_N * MAXC * 64 * 64];   // 32 MB
__device__ float g_pm[Bn * QT_N * MAXC * 64];
__device__ float g_pl[Bn * QT_N * MAXC * 64];

// ---------------------------------------------------------------------------
// Kernel 1: fused QKV projection (at fp32 FFMA roofline; unchanged).
// ---------------------------------------------------------------------------
__global__ __launch_bounds__(256) void qkv_kernel(
    const float* __restrict__ x,
    const float* __restrict__ wq, const float* __restrict__ bq,
    const float* __restrict__ wk, const float* __restrict__ bk,
    const float* __restrict__ wv, const float* __restrict__ bv)
{
    __shared__ float xs[32][64];        // [k][m] transposed x tile
    __shared__ float ws[3][32][64];     // [mtx][k][h]

    const int t  = threadIdx.x;
    const int ty = t >> 4;
    const int tx = t & 15;
    const int m0 = blockIdx.x * 64;

    const float* wptr[3] = {wq, wk, wv};

    float acc[3][4][4];
#pragma unroll
    for (int m = 0; m < 3; m++)
#pragma unroll
        for (int i = 0; i < 4; i++)
#pragma unroll
            for (int j = 0; j < 4; j++)
                acc[m][i][j] = 0.0f;

    for (int k0 = 0; k0 < En; k0 += 32) {
#pragma unroll
        for (int l = 0; l < 2; l++) {
            int idx = t + l * 256;
            int r   = idx >> 3;
            int c4  = idx & 7;
            float4 v4 = *(const float4*)(x + (size_t)(m0 + r) * En + k0 + c4 * 4);
            xs[c4 * 4 + 0][r] = v4.x;
            xs[c4 * 4 + 1][r] = v4.y;
            xs[c4 * 4 + 2][r] = v4.z;
            xs[c4 * 4 + 3][r] = v4.w;
        }
#pragma unroll
        for (int m = 0; m < 3; m++) {
#pragma unroll
            for (int l = 0; l < 2; l++) {
                int idx = t + l * 256;
                int r   = idx >> 4;
                int c4  = idx & 15;
                *(float4*)&ws[m][r][c4 * 4] =
                    *(const float4*)(wptr[m] + (size_t)(k0 + r) * Hn + c4 * 4);
            }
        }
        __syncthreads();

#pragma unroll
        for (int kk = 0; kk < 32; kk++) {
            float a[4];
#pragma unroll
            for (int i = 0; i < 4; i++) a[i] = xs[kk][ty * 4 + i];
#pragma unroll
            for (int m = 0; m < 3; m++) {
                float4 b4 = *(float4*)&ws[m][kk][tx * 4];
#pragma unroll
                for (int i = 0; i < 4; i++) {
                    acc[m][i][0] = fmaf(a[i], b4.x, acc[m][i][0]);
                    acc[m][i][1] = fmaf(a[i], b4.y, acc[m][i][1]);
                    acc[m][i][2] = fmaf(a[i], b4.z, acc[m][i][2]);
                    acc[m][i][3] = fmaf(a[i], b4.w, acc[m][i][3]);
                }
            }
        }
        __syncthreads();
    }

    float* outp[3] = {g_q, g_k, g_v};
    const float* bptr[3] = {bq, bk, bv};
#pragma unroll
    for (int m = 0; m < 3; m++) {
        float4 bb = *(const float4*)(bptr[m] + tx * 4);
#pragma unroll
        for (int i = 0; i < 4; i++) {
            int row = m0 + ty * 4 + i;
            float4 o;
            o.x = acc[m][i][0] + bb.x;
            o.y = acc[m][i][1] + bb.y;
            o.z = acc[m][i][2] + bb.z;
            o.w = acc[m][i][3] + bb.w;
            *(float4*)(outp[m] + (size_t)row * Hn + tx * 4) = o;
        }
    }
}

// ---------------------------------------------------------------------------
// Kernel 2: causal flash attention, split-K partials.
// Block = (chunk, qt, b). Each active block processes <= CHUNK key tiles and
// writes an unnormalized partial (O, m, l) to scratch.
// ---------------------------------------------------------------------------
#define KST_LD 68
#define VS_LD  68

__global__ __launch_bounds__(256) void attn_partial_kernel()
{
    const int chunk = blockIdx.x;
    const int qt    = blockIdx.y;
    const int b     = blockIdx.z;

    const int nt  = qt + 1;              // total key tiles for this q tile
    const int jt0 = chunk * CHUNK;
    if (jt0 >= nt) return;               // inactive split — fast exit
    const int jt1 = min(jt0 + CHUNK, nt);

    extern __shared__ float sm[];
    float* qs  = sm;                     // [64][64]
    float* kst = qs  + 64 * 64;          // [64 h][KST_LD]
    float* vs  = kst + 64 * KST_LD;      // [64 k][VS_LD]
    float* ps  = vs  + 64 * VS_LD;       // [64][64]

    const int t  = threadIdx.x;
    const int ty = t >> 4;
    const int tx = t & 15;
    const int q0 = qt * 64;

    const float* Q = g_q + ((size_t)b * Sn + q0) * Hn;

#pragma unroll
    for (int l = 0; l < 4; l++) {
        int idx = t + l * 256;
        int r   = idx >> 4;
        int h4  = idx & 15;
        float4 v4 = *(const float4*)(Q + (size_t)r * Hn + h4 * 4);
        v4.x *= 0.125f; v4.y *= 0.125f; v4.z *= 0.125f; v4.w *= 0.125f;
        *(float4*)(qs + r * 64 + h4 * 4) = v4;
    }

    float m_i[4], l_i[4], o[4][4];
#pragma unroll
    for (int i = 0; i < 4; i++) {
        m_i[i] = -1e30f;
        l_i[i] = 0.0f;
#pragma unroll
        for (int j = 0; j < 4; j++) o[i][j] = 0.0f;
    }

    for (int jt = jt0; jt < jt1; jt++) {
        const float* K = g_k + ((size_t)b * Sn + jt * 64) * Hn;
        const float* V = g_v + ((size_t)b * Sn + jt * 64) * Hn;

        __syncthreads();
#pragma unroll
        for (int l = 0; l < 4; l++) {
            int idx = t + l * 256;
            int r   = idx >> 4;
            int h4  = idx & 15;
            float4 kv = *(const float4*)(K + (size_t)r * Hn + h4 * 4);
            kst[(h4 * 4 + 0) * KST_LD + r] = kv.x;
            kst[(h4 * 4 + 1) * KST_LD + r] = kv.y;
            kst[(h4 * 4 + 2) * KST_LD + r] = kv.z;
            kst[(h4 * 4 + 3) * KST_LD + r] = kv.w;
            float4 vv = *(const float4*)(V + (size_t)r * Hn + h4 * 4);
            *(float4*)(vs + r * VS_LD + h4 * 4) = vv;
        }
        __syncthreads();

        float s[4][4];
#pragma unroll
        for (int i = 0; i < 4; i++)
#pragma unroll
            for (int j = 0; j < 4; j++) s[i][j] = 0.0f;

#pragma unroll 8
        for (int h = 0; h < 64; h++) {
            float a[4];
#pragma unroll
            for (int i = 0; i < 4; i++) a[i] = qs[(ty * 4 + i) * 64 + h];
            float4 b4 = *(float4*)(kst + h * KST_LD + tx * 4);
#pragma unroll
            for (int i = 0; i < 4; i++) {
                s[i][0] = fmaf(a[i], b4.x, s[i][0]);
                s[i][1] = fmaf(a[i], b4.y, s[i][1]);
                s[i][2] = fmaf(a[i], b4.z, s[i][2]);
                s[i][3] = fmaf(a[i], b4.w, s[i][3]);
            }
        }

        if (jt == qt) {
#pragma unroll
            for (int i = 0; i < 4; i++)
#pragma unroll
                for (int j = 0; j < 4; j++)
                    if (tx * 4 + j > ty * 4 + i) s[i][j] = -1e30f;
        }

        float alpha[4];
#pragma unroll
        for (int i = 0; i < 4; i++) {
            float mx = fmaxf(fmaxf(s[i][0], s[i][1]), fmaxf(s[i][2], s[i][3]));
#pragma unroll
            for (int off = 8; off >= 1; off >>= 1)
                mx = fmaxf(mx, __shfl_xor_sync(0xffffffff, mx, off));
            float mnew = fmaxf(m_i[i], mx);
            alpha[i] = __expf(m_i[i] - mnew);
            float rs = 0.0f;
#pragma unroll
            for (int j = 0; j < 4; j++) {
                s[i][j] = __expf(s[i][j] - mnew);
                rs += s[i][j];
            }
#pragma unroll
            for (int off = 8; off >= 1; off >>= 1)
                rs += __shfl_xor_sync(0xffffffff, rs, off);
            l_i[i] = l_i[i] * alpha[i] + rs;
            m_i[i] = mnew;
        }

#pragma unroll
        for (int i = 0; i < 4; i++)
            *(float4*)(ps + (ty * 4 + i) * 64 + tx * 4) =
                make_float4(s[i][0], s[i][1], s[i][2], s[i][3]);
        __syncthreads();

#pragma unroll
        for (int i = 0; i < 4; i++)
#pragma unroll
            for (int j = 0; j < 4; j++) o[i][j] *= alpha[i];

#pragma unroll 8
        for (int k = 0; k < 64; k++) {
            float a[4];
#pragma unroll
            for (int i = 0; i < 4; i++) a[i] = ps[(ty * 4 + i) * 64 + k];
            float4 b4 = *(float4*)(vs + k * VS_LD + tx * 4);
#pragma unroll
            for (int i = 0; i < 4; i++) {
                o[i][0] = fmaf(a[i], b4.x, o[i][0]);
                o[i][1] = fmaf(a[i], b4.y, o[i][1]);
                o[i][2] = fmaf(a[i], b4.z, o[i][2]);
                o[i][3] = fmaf(a[i], b4.w, o[i][3]);
            }
        }
    }

    // Write unnormalized partial (O, m, l)
    const int slot = ((b * QT_N) + qt) * MAXC + chunk;
    float* po = g_po + (size_t)slot * 64 * 64;
#pragma unroll
    for (int i = 0; i < 4; i++) {
        *(float4*)(po + (ty * 4 + i) * 64 + tx * 4) =
            make_float4(o[i][0], o[i][1], o[i][2], o[i][3]);
        if (tx == 0) {
            g_pm[slot * 64 + ty * 4 + i] = m_i[i];
            g_pl[slot * 64 + ty * 4 + i] = l_i[i];
        }
    }
}

// ---------------------------------------------------------------------------
// Kernel 3: combine partials. Block = (qt, b); 256 threads = 64 rows x 4.
// ---------------------------------------------------------------------------
__global__ __launch_bounds__(256) void attn_combine_kernel(float* __restrict__ y)
{
    const int qt = blockIdx.x;
    const int b  = blockIdx.y;
    const int nc = (qt + CHUNK) / CHUNK;    // ceil((qt+1)/CHUNK)

    const int t  = threadIdx.x;
    const int r  = t >> 2;                  // row 0..63
    const int c0 = (t & 3) * 16;            // 16 cols per thread

    const int base = ((b * QT_N) + qt) * MAXC;

    float M = -1e30f;
#pragma unroll 4
    for (int c = 0; c < nc; c++)
        M = fmaxf(M, g_pm[(base + c) * 64 + r]);

    float w[MAXC];
    float L = 0.0f;
#pragma unroll 4
    for (int c = 0; c < nc; c++) {
        w[c] = __expf(g_pm[(base + c) * 64 + r] - M);
        L += g_pl[(base + c) * 64 + r] * w[c];
    }
    const float inv = 1.0f / L;

    float acc[16];
#pragma unroll
    for (int k = 0; k < 16; k++) acc[k] = 0.0f;

    for (int c = 0; c < nc; c++) {
        const float* po = g_po + (size_t)(base + c) * 64 * 64 + r * 64 + c0;
        const float wc = w[c];
#pragma unroll
        for (int v = 0; v < 4; v++) {
            float4 p4 = *(const float4*)(po + v * 4);
            acc[v * 4 + 0] = fmaf(p4.x, wc, acc[v * 4 + 0]);
            acc[v * 4 + 1] = fmaf(p4.y, wc, acc[v * 4 + 1]);
            acc[v * 4 + 2] = fmaf(p4.z, wc, acc[v * 4 + 2]);
            acc[v * 4 + 3] = fmaf(p4.w, wc, acc[v * 4 + 3]);
        }
    }

    float* Y = y + ((size_t)b * Sn + qt * 64 + r) * Hn + c0;
#pragma unroll
    for (int v = 0; v < 4; v++) {
        float4 ov;
        ov.x = acc[v * 4 + 0] * inv;
        ov.y = acc[v * 4 + 1] * inv;
        ov.z = acc[v * 4 + 2] * inv;
        ov.w = acc[v * 4 + 3] * inv;
        *(float4*)(Y + v * 4) = ov;
    }
}

// ---------------------------------------------------------------------------
extern "C" void kernel_launch(void* const* d_in, const int* in_sizes, int n_in,
                              void* d_out, int out_size)
{
    const float* x  = (const float*)d_in[0];
    const float* wq = (const float*)d_in[1];
    const float* bq = (const float*)d_in[2];
    const float* wk = (const float*)d_in[3];
    const float* bk = (const float*)d_in[4];
    const float* wv = (const float*)d_in[5];
    const float* bv = (const float*)d_in[6];
    float* y = (float*)d_out;

    qkv_kernel<<<Mn / 64, 256>>>(x, wq, bq, wk, bk, wv, bv);

    const int smem_bytes = (64 * 64 + 64 * KST_LD + 64 * VS_LD + 64 * 64) * sizeof(float);
    cudaFuncSetAttribute(attn_partial_kernel, cudaFuncAttributeMaxDynamicSharedMemorySize, smem_bytes);
    attn_partial_kernel<<<dim3(MAXC, QT_N, Bn), 256, smem_bytes>>>();

    attn_combine_kernel<<<dim3(QT_N, Bn), 256>>>(y);
}

// round 4
// speedup vs baseline: 1.5779x; 1.1612x over previous
#include <cuda_runtime.h>
#include <cuda_bf16.h>
#include <cstdint>

#define Bn 8
#define Sn 2048
#define En 1024
#define Hn 64
#define Mn (Bn * Sn)

#define QT_N   32
#define CHUNK  4
#define MAXC   8

// Scratch (allocation-free device globals)
__device__ float g_q[Mn * Hn];
__device__ float g_k[Mn * Hn];
__device__ float g_v[Mn * Hn];

__device__ float g_po[(size_t)Bn * QT_N * MAXC * 64 * 64];
__device__ float g_pm[Bn * QT_N * MAXC * 64];
__device__ float g_pl[Bn * QT_N * MAXC * 64];

// Pre-converted weights: [tile = mat*2 + (0=hi,1=lo)][n (64)][k (1024)] bf16
__device__ __nv_bfloat16 g_wt[6 * 64 * En];

// ---------------------------------------------------------------------------
// mma.sync helper (portable HMMA, no arch-specific ISA)
// D(16x8,f32) += A(16x16,bf16 row) * B(16x8,bf16 col)
// ---------------------------------------------------------------------------
__device__ __forceinline__ void mma16816(float* c, const uint32_t* a,
                                         uint32_t b0, uint32_t b1) {
    asm volatile(
        "mma.sync.aligned.m16n8k16.row.col.f32.bf16.bf16.f32 "
        "{%0,%1,%2,%3}, {%4,%5,%6,%7}, {%8,%9}, {%0,%1,%2,%3};"
        : "+f"(c[0]), "+f"(c[1]), "+f"(c[2]), "+f"(c[3])
        : "r"(a[0]), "r"(a[1]), "r"(a[2]), "r"(a[3]), "r"(b0), "r"(b1));
}

__device__ __forceinline__ uint32_t pack2bf(float f0, float f1) {
    __nv_bfloat16 b0 = __float2bfloat16(f0);
    __nv_bfloat16 b1 = __float2bfloat16(f1);
    return (uint32_t)__bfloat16_as_ushort(b0) | ((uint32_t)__bfloat16_as_ushort(b1) << 16);
}

// ---------------------------------------------------------------------------
// Kernel 0: convert+transpose+split weights -> g_wt[mat*2+h][n][k] bf16
// ---------------------------------------------------------------------------
__global__ __launch_bounds__(256) void conv_w_kernel(
    const float* __restrict__ wq, const float* __restrict__ wk, const float* __restrict__ wv)
{
    const float* wsrc[3] = {wq, wk, wv};
    int id = blockIdx.x * 256 + threadIdx.x;     // over 3 * 64 * 1024
    if (id >= 3 * Hn * En) return;
    int mat = id / (Hn * En);
    int rem = id % (Hn * En);
    int n = rem / En;
    int k = rem % En;
    float v = wsrc[mat][(size_t)k * Hn + n];
    __nv_bfloat16 hi = __float2bfloat16(v);
    __nv_bfloat16 lo = __float2bfloat16(v - __bfloat162float(hi));
    g_wt[((size_t)(mat * 2 + 0) * Hn + n) * En + k] = hi;
    g_wt[((size_t)(mat * 2 + 1) * Hn + n) * En + k] = lo;
}

// ---------------------------------------------------------------------------
// Kernel 1: QKV projection via mma.sync bf16 with hi/lo compensation.
// Grid = 256 (M tile 64), 128 threads = 4 warps; warp = 16 rows x 192 cols.
// ---------------------------------------------------------------------------
#define KC   32          // k per chunk
#define ALD  40          // row stride in bf16 elements (32 + 8 pad) -> conflict-free

__global__ __launch_bounds__(128) void qkv_mma_kernel(
    const float* __restrict__ x,
    const float* __restrict__ bq, const float* __restrict__ bk, const float* __restrict__ bv)
{
    __shared__ __nv_bfloat16 sAh[64 * ALD];
    __shared__ __nv_bfloat16 sAl[64 * ALD];
    __shared__ __nv_bfloat16 sB[6 * 64 * ALD];

    const int t    = threadIdx.x;
    const int w    = t >> 5;
    const int lane = t & 31;
    const int g    = lane >> 2;       // 0..7
    const int tt   = lane & 3;        // 0..3
    const int m0   = blockIdx.x * 64;

    float acc[3][8][4];
#pragma unroll
    for (int m = 0; m < 3; m++)
#pragma unroll
        for (int n = 0; n < 8; n++)
#pragma unroll
            for (int i = 0; i < 4; i++)
                acc[m][n][i] = 0.0f;

    for (int c = 0; c < En / KC; c++) {
        const int k0 = c * KC;
        __syncthreads();

        // Stage x tile [64 rows][32 k] -> hi/lo bf16. Thread: row=t>>1, ks=(t&1)*16.
        {
            const int r  = t >> 1;
            const int ks = (t & 1) * 16;
            const float* xp = x + (size_t)(m0 + r) * En + k0 + ks;
            float f[16];
#pragma unroll
            for (int j = 0; j < 4; j++) {
                float4 v4 = *(const float4*)(xp + j * 4);
                f[j * 4 + 0] = v4.x; f[j * 4 + 1] = v4.y;
                f[j * 4 + 2] = v4.z; f[j * 4 + 3] = v4.w;
            }
            uint32_t hi[8], lo[8];
#pragma unroll
            for (int j = 0; j < 8; j++) {
                float f0 = f[j * 2], f1 = f[j * 2 + 1];
                float h0 = __bfloat162float(__float2bfloat16(f0));
                float h1 = __bfloat162float(__float2bfloat16(f1));
                hi[j] = pack2bf(f0, f1);
                lo[j] = pack2bf(f0 - h0, f1 - h1);
            }
            uint32_t eo = (uint32_t)(r * ALD + ks);
            *(uint4*)&sAh[eo]     = make_uint4(hi[0], hi[1], hi[2], hi[3]);
            *(uint4*)&sAh[eo + 8] = make_uint4(hi[4], hi[5], hi[6], hi[7]);
            *(uint4*)&sAl[eo]     = make_uint4(lo[0], lo[1], lo[2], lo[3]);
            *(uint4*)&sAl[eo + 8] = make_uint4(lo[4], lo[5], lo[6], lo[7]);
        }

        // Stage B: 6 tiles x 64 n-rows x 32 k bf16 (384 rows, 3 per thread)
#pragma unroll
        for (int rr = 0; rr < 3; rr++) {
            int r = t + rr * 128;     // tile*64 + n
            const __nv_bfloat16* wp = g_wt + (size_t)r * En + k0;
            uint4 v0 = *(const uint4*)wp;
            uint4 v1 = *(const uint4*)(wp + 8);
            uint4 v2 = *(const uint4*)(wp + 16);
            uint4 v3 = *(const uint4*)(wp + 24);
            uint32_t eo = (uint32_t)(r * ALD);
            *(uint4*)&sB[eo]      = v0;
            *(uint4*)&sB[eo + 8]  = v1;
            *(uint4*)&sB[eo + 16] = v2;
            *(uint4*)&sB[eo + 24] = v3;
        }
        __syncthreads();

        // Compute: 2 k16 steps
#pragma unroll
        for (int ks = 0; ks < 2; ks++) {
            const int kb = ks * 16;
            uint32_t aH[4], aL[4];
            {
                int r0 = (w * 16 + g) * ALD + kb + 2 * tt;
                int r1 = (w * 16 + g + 8) * ALD + kb + 2 * tt;
                aH[0] = *(const uint32_t*)&sAh[r0];
                aH[1] = *(const uint32_t*)&sAh[r1];
                aH[2] = *(const uint32_t*)&sAh[r0 + 8];
                aH[3] = *(const uint32_t*)&sAh[r1 + 8];
                aL[0] = *(const uint32_t*)&sAl[r0];
                aL[1] = *(const uint32_t*)&sAl[r1];
                aL[2] = *(const uint32_t*)&sAl[r0 + 8];
                aL[3] = *(const uint32_t*)&sAl[r1 + 8];
            }
#pragma unroll
            for (int mat = 0; mat < 3; mat++) {
#pragma unroll
                for (int n8 = 0; n8 < 8; n8++) {
                    int bh = ((mat * 2 + 0) * 64 + n8 * 8 + g) * ALD + kb + 2 * tt;
                    int bl = ((mat * 2 + 1) * 64 + n8 * 8 + g) * ALD + kb + 2 * tt;
                    uint32_t bH0 = *(const uint32_t*)&sB[bh];
                    uint32_t bH1 = *(const uint32_t*)&sB[bh + 8];
                    uint32_t bL0 = *(const uint32_t*)&sB[bl];
                    uint32_t bL1 = *(const uint32_t*)&sB[bl + 8];
                    mma16816(acc[mat][n8], aH, bH0, bH1);
                    mma16816(acc[mat][n8], aH, bL0, bL1);
                    mma16816(acc[mat][n8], aL, bH0, bH1);
                }
            }
        }
    }

    // Epilogue: bias + store fp32
    float* outp[3] = {g_q, g_k, g_v};
    const float* bias[3] = {bq, bk, bv};
    const int r0 = m0 + w * 16 + g;
#pragma unroll
    for (int mat = 0; mat < 3; mat++) {
        const float* bp = bias[mat];
        float* op = outp[mat];
#pragma unroll
        for (int n8 = 0; n8 < 8; n8++) {
            int col = n8 * 8 + 2 * tt;
            float b0 = __ldg(bp + col), b1 = __ldg(bp + col + 1);
            float2 v0 = make_float2(acc[mat][n8][0] + b0, acc[mat][n8][1] + b1);
            float2 v1 = make_float2(acc[mat][n8][2] + b0, acc[mat][n8][3] + b1);
            *(float2*)(op + (size_t)r0 * Hn + col)       = v0;
            *(float2*)(op + (size_t)(r0 + 8) * Hn + col) = v1;
        }
    }
}

// ---------------------------------------------------------------------------
// Kernel 2: causal flash attention, split-K partials (unchanged).
// ---------------------------------------------------------------------------
#define KST_LD 68
#define VS_LD  68

__global__ __launch_bounds__(256) void attn_partial_kernel()
{
    const int chunk = blockIdx.x;
    const int qt    = blockIdx.y;
    const int b     = blockIdx.z;

    const int nt  = qt + 1;
    const int jt0 = chunk * CHUNK;
    if (jt0 >= nt) return;
    const int jt1 = min(jt0 + CHUNK, nt);

    extern __shared__ float sm[];
    float* qs  = sm;
    float* kst = qs  + 64 * 64;
    float* vs  = kst + 64 * KST_LD;
    float* ps  = vs  + 64 * VS_LD;

    const int t  = threadIdx.x;
    const int ty = t >> 4;
    const int tx = t & 15;
    const int q0 = qt * 64;

    const float* Q = g_q + ((size_t)b * Sn + q0) * Hn;

#pragma unroll
    for (int l = 0; l < 4; l++) {
        int idx = t + l * 256;
        int r   = idx >> 4;
        int h4  = idx & 15;
        float4 v4 = *(const float4*)(Q + (size_t)r * Hn + h4 * 4);
        v4.x *= 0.125f; v4.y *= 0.125f; v4.z *= 0.125f; v4.w *= 0.125f;
        *(float4*)(qs + r * 64 + h4 * 4) = v4;
    }

    float m_i[4], l_i[4], o[4][4];
#pragma unroll
    for (int i = 0; i < 4; i++) {
        m_i[i] = -1e30f;
        l_i[i] = 0.0f;
#pragma unroll
        for (int j = 0; j < 4; j++) o[i][j] = 0.0f;
    }

    for (int jt = jt0; jt < jt1; jt++) {
        const float* K = g_k + ((size_t)b * Sn + jt * 64) * Hn;
        const float* V = g_v + ((size_t)b * Sn + jt * 64) * Hn;

        __syncthreads();
#pragma unroll
        for (int l = 0; l < 4; l++) {
            int idx = t + l * 256;
            int r   = idx >> 4;
            int h4  = idx & 15;
            float4 kv = *(const float4*)(K + (size_t)r * Hn + h4 * 4);
            kst[(h4 * 4 + 0) * KST_LD + r] = kv.x;
            kst[(h4 * 4 + 1) * KST_LD + r] = kv.y;
            kst[(h4 * 4 + 2) * KST_LD + r] = kv.z;
            kst[(h4 * 4 + 3) * KST_LD + r] = kv.w;
            float4 vv = *(const float4*)(V + (size_t)r * Hn + h4 * 4);
            *(float4*)(vs + r * VS_LD + h4 * 4) = vv;
        }
        __syncthreads();

        float s[4][4];
#pragma unroll
        for (int i = 0; i < 4; i++)
#pragma unroll
            for (int j = 0; j < 4; j++) s[i][j] = 0.0f;

#pragma unroll 8
        for (int h = 0; h < 64; h++) {
            float a[4];
#pragma unroll
            for (int i = 0; i < 4; i++) a[i] = qs[(ty * 4 + i) * 64 + h];
            float4 b4 = *(float4*)(kst + h * KST_LD + tx * 4);
#pragma unroll
            for (int i = 0; i < 4; i++) {
                s[i][0] = fmaf(a[i], b4.x, s[i][0]);
                s[i][1] = fmaf(a[i], b4.y, s[i][1]);
                s[i][2] = fmaf(a[i], b4.z, s[i][2]);
                s[i][3] = fmaf(a[i], b4.w, s[i][3]);
            }
        }

        if (jt == qt) {
#pragma unroll
            for (int i = 0; i < 4; i++)
#pragma unroll
                for (int j = 0; j < 4; j++)
                    if (tx * 4 + j > ty * 4 + i) s[i][j] = -1e30f;
        }

        float alpha[4];
#pragma unroll
        for (int i = 0; i < 4; i++) {
            float mx = fmaxf(fmaxf(s[i][0], s[i][1]), fmaxf(s[i][2], s[i][3]));
#pragma unroll
            for (int off = 8; off >= 1; off >>= 1)
                mx = fmaxf(mx, __shfl_xor_sync(0xffffffff, mx, off));
            float mnew = fmaxf(m_i[i], mx);
            alpha[i] = __expf(m_i[i] - mnew);
            float rs = 0.0f;
#pragma unroll
            for (int j = 0; j < 4; j++) {
                s[i][j] = __expf(s[i][j] - mnew);
                rs += s[i][j];
            }
#pragma unroll
            for (int off = 8; off >= 1; off >>= 1)
                rs += __shfl_xor_sync(0xffffffff, rs, off);
            l_i[i] = l_i[i] * alpha[i] + rs;
            m_i[i] = mnew;
        }

#pragma unroll
        for (int i = 0; i < 4; i++)
            *(float4*)(ps + (ty * 4 + i) * 64 + tx * 4) =
                make_float4(s[i][0], s[i][1], s[i][2], s[i][3]);
        __syncthreads();

#pragma unroll
        for (int i = 0; i < 4; i++)
#pragma unroll
            for (int j = 0; j < 4; j++) o[i][j] *= alpha[i];

#pragma unroll 8
        for (int k = 0; k < 64; k++) {
            float a[4];
#pragma unroll
            for (int i = 0; i < 4; i++) a[i] = ps[(ty * 4 + i) * 64 + k];
            float4 b4 = *(float4*)(vs + k * VS_LD + tx * 4);
#pragma unroll
            for (int i = 0; i < 4; i++) {
                o[i][0] = fmaf(a[i], b4.x, o[i][0]);
                o[i][1] = fmaf(a[i], b4.y, o[i][1]);
                o[i][2] = fmaf(a[i], b4.z, o[i][2]);
                o[i][3] = fmaf(a[i], b4.w, o[i][3]);
            }
        }
    }

    const int slot = ((b * QT_N) + qt) * MAXC + chunk;
    float* po = g_po + (size_t)slot * 64 * 64;
#pragma unroll
    for (int i = 0; i < 4; i++) {
        *(float4*)(po + (ty * 4 + i) * 64 + tx * 4) =
            make_float4(o[i][0], o[i][1], o[i][2], o[i][3]);
        if (tx == 0) {
            g_pm[slot * 64 + ty * 4 + i] = m_i[i];
            g_pl[slot * 64 + ty * 4 + i] = l_i[i];
        }
    }
}

// ---------------------------------------------------------------------------
// Kernel 3: combine partials (unchanged).
// ---------------------------------------------------------------------------
__global__ __launch_bounds__(256) void attn_combine_kernel(float* __restrict__ y)
{
    const int qt = blockIdx.x;
    const int b  = blockIdx.y;
    const int nc = (qt + CHUNK) / CHUNK;

    const int t  = threadIdx.x;
    const int r  = t >> 2;
    const int c0 = (t & 3) * 16;

    const int base = ((b * QT_N) + qt) * MAXC;

    float M = -1e30f;
#pragma unroll 4
    for (int c = 0; c < nc; c++)
        M = fmaxf(M, g_pm[(base + c) * 64 + r]);

    float w[MAXC];
    float L = 0.0f;
#pragma unroll 4
    for (int c = 0; c < nc; c++) {
        w[c] = __expf(g_pm[(base + c) * 64 + r] - M);
        L += g_pl[(base + c) * 64 + r] * w[c];
    }
    const float inv = 1.0f / L;

    float acc[16];
#pragma unroll
    for (int k = 0; k < 16; k++) acc[k] = 0.0f;

    for (int c = 0; c < nc; c++) {
        const float* po = g_po + (size_t)(base + c) * 64 * 64 + r * 64 + c0;
        const float wc = w[c];
#pragma unroll
        for (int v = 0; v < 4; v++) {
            float4 p4 = *(const float4*)(po + v * 4);
            acc[v * 4 + 0] = fmaf(p4.x, wc, acc[v * 4 + 0]);
            acc[v * 4 + 1] = fmaf(p4.y, wc, acc[v * 4 + 1]);
            acc[v * 4 + 2] = fmaf(p4.z, wc, acc[v * 4 + 2]);
            acc[v * 4 + 3] = fmaf(p4.w, wc, acc[v * 4 + 3]);
        }
    }

    float* Y = y + ((size_t)b * Sn + qt * 64 + r) * Hn + c0;
#pragma unroll
    for (int v = 0; v < 4; v++) {
        float4 ov;
        ov.x = acc[v * 4 + 0] * inv;
        ov.y = acc[v * 4 + 1] * inv;
        ov.z = acc[v * 4 + 2] * inv;
        ov.w = acc[v * 4 + 3] * inv;
        *(float4*)(Y + v * 4) = ov;
    }
}

// ---------------------------------------------------------------------------
extern "C" void kernel_launch(void* const* d_in, const int* in_sizes, int n_in,
                              void* d_out, int out_size)
{
    const float* x  = (const float*)d_in[0];
    const float* wq = (const float*)d_in[1];
    const float* bq = (const float*)d_in[2];
    const float* wk = (const float*)d_in[3];
    const float* bk = (const float*)d_in[4];
    const float* wv = (const float*)d_in[5];
    const float* bv = (const float*)d_in[6];
    float* y = (float*)d_out;

    conv_w_kernel<<<(3 * Hn * En + 255) / 256, 256>>>(wq, wk, wv);

    qkv_mma_kernel<<<Mn / 64, 128>>>(x, bq, bk, bv);

    const int smem_bytes = (64 * 64 + 64 * KST_LD + 64 * VS_LD + 64 * 64) * sizeof(float);
    cudaFuncSetAttribute(attn_partial_kernel, cudaFuncAttributeMaxDynamicSharedMemorySize, smem_bytes);
    attn_partial_kernel<<<dim3(MAXC, QT_N, Bn), 256, smem_bytes>>>();

    attn_combine_kernel<<<dim3(QT_N, Bn), 256>>>(y);
}

// round 5
// speedup vs baseline: 1.5884x; 1.0067x over previous
#include <cuda_runtime.h>
#include <cuda_bf16.h>
#include <cstdint>

#define Bn 8
#define Sn 2048
#define En 1024
#define Hn 64
#define Mn (Bn * Sn)

#define QT_N   32
#define CHUNK  4
#define MAXC   8

// Scratch (allocation-free device globals)
__device__ float g_q[Mn * Hn];
__device__ float g_k[Mn * Hn];
__device__ float g_v[Mn * Hn];

__device__ float g_po[(size_t)Bn * QT_N * MAXC * 64 * 64];
__device__ float g_pm[Bn * QT_N * MAXC * 64];
__device__ float g_pl[Bn * QT_N * MAXC * 64];

// Pre-converted weights: [tile = mat*2 + (0=hi,1=lo)][n (64)][k (1024)] bf16
__device__ __nv_bfloat16 g_wt[6 * 64 * En];

// ---------------------------------------------------------------------------
// mma.sync helper (portable HMMA, no arch-specific ISA)
// D(16x8,f32) += A(16x16,bf16 row) * B(16x8,bf16 col)
// ---------------------------------------------------------------------------
__device__ __forceinline__ void mma16816(float* c, const uint32_t* a,
                                         uint32_t b0, uint32_t b1) {
    asm volatile(
        "mma.sync.aligned.m16n8k16.row.col.f32.bf16.bf16.f32 "
        "{%0,%1,%2,%3}, {%4,%5,%6,%7}, {%8,%9}, {%0,%1,%2,%3};"
        : "+f"(c[0]), "+f"(c[1]), "+f"(c[2]), "+f"(c[3])
        : "r"(a[0]), "r"(a[1]), "r"(a[2]), "r"(a[3]), "r"(b0), "r"(b1));
}

__device__ __forceinline__ uint32_t pack2bf(float f0, float f1) {
    __nv_bfloat16 b0 = __float2bfloat16(f0);
    __nv_bfloat16 b1 = __float2bfloat16(f1);
    return (uint32_t)__bfloat16_as_ushort(b0) | ((uint32_t)__bfloat16_as_ushort(b1) << 16);
}

// ---------------------------------------------------------------------------
// Kernel 0: convert+transpose+split weights -> g_wt[mat*2+h][n][k] bf16
// ---------------------------------------------------------------------------
__global__ __launch_bounds__(256) void conv_w_kernel(
    const float* __restrict__ wq, const float* __restrict__ wk, const float* __restrict__ wv)
{
    const float* wsrc[3] = {wq, wk, wv};
    int id = blockIdx.x * 256 + threadIdx.x;     // over 3 * 64 * 1024
    if (id >= 3 * Hn * En) return;
    int mat = id / (Hn * En);
    int rem = id % (Hn * En);
    int n = rem / En;
    int k = rem % En;
    float v = wsrc[mat][(size_t)k * Hn + n];
    __nv_bfloat16 hi = __float2bfloat16(v);
    __nv_bfloat16 lo = __float2bfloat16(v - __bfloat162float(hi));
    g_wt[((size_t)(mat * 2 + 0) * Hn + n) * En + k] = hi;
    g_wt[((size_t)(mat * 2 + 1) * Hn + n) * En + k] = lo;
}

// ---------------------------------------------------------------------------
// Kernel 1: QKV projection via mma.sync bf16 with hi/lo compensation.
// Grid = 256 (M tile 64), 128 threads = 4 warps; warp = 16 rows x 192 cols.
// ---------------------------------------------------------------------------
#define KC   32          // k per chunk
#define ALD  40          // row stride in bf16 elements (32 + 8 pad) -> conflict-free

__global__ __launch_bounds__(128) void qkv_mma_kernel(
    const float* __restrict__ x,
    const float* __restrict__ bq, const float* __restrict__ bk, const float* __restrict__ bv)
{
    __shared__ __nv_bfloat16 sAh[64 * ALD];
    __shared__ __nv_bfloat16 sAl[64 * ALD];
    __shared__ __nv_bfloat16 sB[6 * 64 * ALD];

    const int t    = threadIdx.x;
    const int w    = t >> 5;
    const int lane = t & 31;
    const int g    = lane >> 2;       // 0..7
    const int tt   = lane & 3;        // 0..3
    const int m0   = blockIdx.x * 64;

    float acc[3][8][4];
#pragma unroll
    for (int m = 0; m < 3; m++)
#pragma unroll
        for (int n = 0; n < 8; n++)
#pragma unroll
            for (int i = 0; i < 4; i++)
                acc[m][n][i] = 0.0f;

    for (int c = 0; c < En / KC; c++) {
        const int k0 = c * KC;
        __syncthreads();

        // Stage x tile [64 rows][32 k] -> hi/lo bf16. Thread: row=t>>1, ks=(t&1)*16.
        {
            const int r  = t >> 1;
            const int ks = (t & 1) * 16;
            const float* xp = x + (size_t)(m0 + r) * En + k0 + ks;
            float f[16];
#pragma unroll
            for (int j = 0; j < 4; j++) {
                float4 v4 = *(const float4*)(xp + j * 4);
                f[j * 4 + 0] = v4.x; f[j * 4 + 1] = v4.y;
                f[j * 4 + 2] = v4.z; f[j * 4 + 3] = v4.w;
            }
            uint32_t hi[8], lo[8];
#pragma unroll
            for (int j = 0; j < 8; j++) {
                float f0 = f[j * 2], f1 = f[j * 2 + 1];
                float h0 = __bfloat162float(__float2bfloat16(f0));
                float h1 = __bfloat162float(__float2bfloat16(f1));
                hi[j] = pack2bf(f0, f1);
                lo[j] = pack2bf(f0 - h0, f1 - h1);
            }
            uint32_t eo = (uint32_t)(r * ALD + ks);
            *(uint4*)&sAh[eo]     = make_uint4(hi[0], hi[1], hi[2], hi[3]);
            *(uint4*)&sAh[eo + 8] = make_uint4(hi[4], hi[5], hi[6], hi[7]);
            *(uint4*)&sAl[eo]     = make_uint4(lo[0], lo[1], lo[2], lo[3]);
            *(uint4*)&sAl[eo + 8] = make_uint4(lo[4], lo[5], lo[6], lo[7]);
        }

        // Stage B: 6 tiles x 64 n-rows x 32 k bf16 (384 rows, 3 per thread)
#pragma unroll
        for (int rr = 0; rr < 3; rr++) {
            int r = t + rr * 128;     // tile*64 + n
            const __nv_bfloat16* wp = g_wt + (size_t)r * En + k0;
            uint4 v0 = *(const uint4*)wp;
            uint4 v1 = *(const uint4*)(wp + 8);
            uint4 v2 = *(const uint4*)(wp + 16);
            uint4 v3 = *(const uint4*)(wp + 24);
            uint32_t eo = (uint32_t)(r * ALD);
            *(uint4*)&sB[eo]      = v0;
            *(uint4*)&sB[eo + 8]  = v1;
            *(uint4*)&sB[eo + 16] = v2;
            *(uint4*)&sB[eo + 24] = v3;
        }
        __syncthreads();

        // Compute: 2 k16 steps
#pragma unroll
        for (int ks = 0; ks < 2; ks++) {
            const int kb = ks * 16;
            uint32_t aH[4], aL[4];
            {
                int r0 = (w * 16 + g) * ALD + kb + 2 * tt;
                int r1 = (w * 16 + g + 8) * ALD + kb + 2 * tt;
                aH[0] = *(const uint32_t*)&sAh[r0];
                aH[1] = *(const uint32_t*)&sAh[r1];
                aH[2] = *(const uint32_t*)&sAh[r0 + 8];
                aH[3] = *(const uint32_t*)&sAh[r1 + 8];
                aL[0] = *(const uint32_t*)&sAl[r0];
                aL[1] = *(const uint32_t*)&sAl[r1];
                aL[2] = *(const uint32_t*)&sAl[r0 + 8];
                aL[3] = *(const uint32_t*)&sAl[r1 + 8];
            }
#pragma unroll
            for (int mat = 0; mat < 3; mat++) {
#pragma unroll
                for (int n8 = 0; n8 < 8; n8++) {
                    int bh = ((mat * 2 + 0) * 64 + n8 * 8 + g) * ALD + kb + 2 * tt;
                    int bl = ((mat * 2 + 1) * 64 + n8 * 8 + g) * ALD + kb + 2 * tt;
                    uint32_t bH0 = *(const uint32_t*)&sB[bh];
                    uint32_t bH1 = *(const uint32_t*)&sB[bh + 8];
                    uint32_t bL0 = *(const uint32_t*)&sB[bl];
                    uint32_t bL1 = *(const uint32_t*)&sB[bl + 8];
                    mma16816(acc[mat][n8], aH, bH0, bH1);
                    mma16816(acc[mat][n8], aH, bL0, bL1);
                    mma16816(acc[mat][n8], aL, bH0, bH1);
                }
            }
        }
    }

    // Epilogue: bias + store fp32
    float* outp[3] = {g_q, g_k, g_v};
    const float* bias[3] = {bq, bk, bv};
    const int r0 = m0 + w * 16 + g;
#pragma unroll
    for (int mat = 0; mat < 3; mat++) {
        const float* bp = bias[mat];
        float* op = outp[mat];
#pragma unroll
        for (int n8 = 0; n8 < 8; n8++) {
            int col = n8 * 8 + 2 * tt;
            float b0 = __ldg(bp + col), b1 = __ldg(bp + col + 1);
            float2 v0 = make_float2(acc[mat][n8][0] + b0, acc[mat][n8][1] + b1);
            float2 v1 = make_float2(acc[mat][n8][2] + b0, acc[mat][n8][3] + b1);
            *(float2*)(op + (size_t)r0 * Hn + col)       = v0;
            *(float2*)(op + (size_t)(r0 + 8) * Hn + col) = v1;
        }
    }
}

// ---------------------------------------------------------------------------
// Kernel 2: causal flash attention, split-K partials (unchanged).
// ---------------------------------------------------------------------------
#define KST_LD 68
#define VS_LD  68

__global__ __launch_bounds__(256) void attn_partial_kernel()
{
    const int chunk = blockIdx.x;
    const int qt    = blockIdx.y;
    const int b     = blockIdx.z;

    const int nt  = qt + 1;
    const int jt0 = chunk * CHUNK;
    if (jt0 >= nt) return;
    const int jt1 = min(jt0 + CHUNK, nt);

    extern __shared__ float sm[];
    float* qs  = sm;
    float* kst = qs  + 64 * 64;
    float* vs  = kst + 64 * KST_LD;
    float* ps  = vs  + 64 * VS_LD;

    const int t  = threadIdx.x;
    const int ty = t >> 4;
    const int tx = t & 15;
    const int q0 = qt * 64;

    const float* Q = g_q + ((size_t)b * Sn + q0) * Hn;

#pragma unroll
    for (int l = 0; l < 4; l++) {
        int idx = t + l * 256;
        int r   = idx >> 4;
        int h4  = idx & 15;
        float4 v4 = *(const float4*)(Q + (size_t)r * Hn + h4 * 4);
        v4.x *= 0.125f; v4.y *= 0.125f; v4.z *= 0.125f; v4.w *= 0.125f;
        *(float4*)(qs + r * 64 + h4 * 4) = v4;
    }

    float m_i[4], l_i[4], o[4][4];
#pragma unroll
    for (int i = 0; i < 4; i++) {
        m_i[i] = -1e30f;
        l_i[i] = 0.0f;
#pragma unroll
        for (int j = 0; j < 4; j++) o[i][j] = 0.0f;
    }

    for (int jt = jt0; jt < jt1; jt++) {
        const float* K = g_k + ((size_t)b * Sn + jt * 64) * Hn;
        const float* V = g_v + ((size_t)b * Sn + jt * 64) * Hn;

        __syncthreads();
#pragma unroll
        for (int l = 0; l < 4; l++) {
            int idx = t + l * 256;
            int r   = idx >> 4;
            int h4  = idx & 15;
            float4 kv = *(const float4*)(K + (size_t)r * Hn + h4 * 4);
            kst[(h4 * 4 + 0) * KST_LD + r] = kv.x;
            kst[(h4 * 4 + 1) * KST_LD + r] = kv.y;
            kst[(h4 * 4 + 2) * KST_LD + r] = kv.z;
            kst[(h4 * 4 + 3) * KST_LD + r] = kv.w;
            float4 vv = *(const float4*)(V + (size_t)r * Hn + h4 * 4);
            *(float4*)(vs + r * VS_LD + h4 * 4) = vv;
        }
        __syncthreads();

        float s[4][4];
#pragma unroll
        for (int i = 0; i < 4; i++)
#pragma unroll
            for (int j = 0; j < 4; j++) s[i][j] = 0.0f;

#pragma unroll 8
        for (int h = 0; h < 64; h++) {
            float a[4];
#pragma unroll
            for (int i = 0; i < 4; i++) a[i] = qs[(ty * 4 + i) * 64 + h];
            float4 b4 = *(float4*)(kst + h * KST_LD + tx * 4);
#pragma unroll
            for (int i = 0; i < 4; i++) {
                s[i][0] = fmaf(a[i], b4.x, s[i][0]);
                s[i][1] = fmaf(a[i], b4.y, s[i][1]);
                s[i][2] = fmaf(a[i], b4.z, s[i][2]);
                s[i][3] = fmaf(a[i], b4.w, s[i][3]);
            }
        }

        if (jt == qt) {
#pragma unroll
            for (int i = 0; i < 4; i++)
#pragma unroll
                for (int j = 0; j < 4; j++)
                    if (tx * 4 + j > ty * 4 + i) s[i][j] = -1e30f;
        }

        float alpha[4];
#pragma unroll
        for (int i = 0; i < 4; i++) {
            float mx = fmaxf(fmaxf(s[i][0], s[i][1]), fmaxf(s[i][2], s[i][3]));
#pragma unroll
            for (int off = 8; off >= 1; off >>= 1)
                mx = fmaxf(mx, __shfl_xor_sync(0xffffffff, mx, off));
            float mnew = fmaxf(m_i[i], mx);
            alpha[i] = __expf(m_i[i] - mnew);
            float rs = 0.0f;
#pragma unroll
            for (int j = 0; j < 4; j++) {
                s[i][j] = __expf(s[i][j] - mnew);
                rs += s[i][j];
            }
#pragma unroll
            for (int off = 8; off >= 1; off >>= 1)
                rs += __shfl_xor_sync(0xffffffff, rs, off);
            l_i[i] = l_i[i] * alpha[i] + rs;
            m_i[i] = mnew;
        }

#pragma unroll
        for (int i = 0; i < 4; i++)
            *(float4*)(ps + (ty * 4 + i) * 64 + tx * 4) =
                make_float4(s[i][0], s[i][1], s[i][2], s[i][3]);
        __syncthreads();

#pragma unroll
        for (int i = 0; i < 4; i++)
#pragma unroll
            for (int j = 0; j < 4; j++) o[i][j] *= alpha[i];

#pragma unroll 8
        for (int k = 0; k < 64; k++) {
            float a[4];
#pragma unroll
            for (int i = 0; i < 4; i++) a[i] = ps[(ty * 4 + i) * 64 + k];
            float4 b4 = *(float4*)(vs + k * VS_LD + tx * 4);
#pragma unroll
            for (int i = 0; i < 4; i++) {
                o[i][0] = fmaf(a[i], b4.x, o[i][0]);
                o[i][1] = fmaf(a[i], b4.y, o[i][1]);
                o[i][2] = fmaf(a[i], b4.z, o[i][2]);
                o[i][3] = fmaf(a[i], b4.w, o[i][3]);
            }
        }
    }

    const int slot = ((b * QT_N) + qt) * MAXC + chunk;
    float* po = g_po + (size_t)slot * 64 * 64;
#pragma unroll
    for (int i = 0; i < 4; i++) {
        *(float4*)(po + (ty * 4 + i) * 64 + tx * 4) =
            make_float4(o[i][0], o[i][1], o[i][2], o[i][3]);
        if (tx == 0) {
            g_pm[slot * 64 + ty * 4 + i] = m_i[i];
            g_pl[slot * 64 + ty * 4 + i] = l_i[i];
        }
    }
}

// ---------------------------------------------------------------------------
// Kernel 3: combine partials (unchanged).
// ---------------------------------------------------------------------------
__global__ __launch_bounds__(256) void attn_combine_kernel(float* __restrict__ y)
{
    const int qt = blockIdx.x;
    const int b  = blockIdx.y;
    const int nc = (qt + CHUNK) / CHUNK;

    const int t  = threadIdx.x;
    const int r  = t >> 2;
    const int c0 = (t & 3) * 16;

    const int base = ((b * QT_N) + qt) * MAXC;

    float M = -1e30f;
#pragma unroll 4
    for (int c = 0; c < nc; c++)
        M = fmaxf(M, g_pm[(base + c) * 64 + r]);

    float w[MAXC];
    float L = 0.0f;
#pragma unroll 4
    for (int c = 0; c < nc; c++) {
        w[c] = __expf(g_pm[(base + c) * 64 + r] - M);
        L += g_pl[(base + c) * 64 + r] * w[c];
    }
    const float inv = 1.0f / L;

    float acc[16];
#pragma unroll
    for (int k = 0; k < 16; k++) acc[k] = 0.0f;

    for (int c = 0; c < nc; c++) {
        const float* po = g_po + (size_t)(base + c) * 64 * 64 + r * 64 + c0;
        const float wc = w[c];
#pragma unroll
        for (int v = 0; v < 4; v++) {
            float4 p4 = *(const float4*)(po + v * 4);
            acc[v * 4 + 0] = fmaf(p4.x, wc, acc[v * 4 + 0]);
            acc[v * 4 + 1] = fmaf(p4.y, wc, acc[v * 4 + 1]);
            acc[v * 4 + 2] = fmaf(p4.z, wc, acc[v * 4 + 2]);
            acc[v * 4 + 3] = fmaf(p4.w, wc, acc[v * 4 + 3]);
        }
    }

    float* Y = y + ((size_t)b * Sn + qt * 64 + r) * Hn + c0;
#pragma unroll
    for (int v = 0; v < 4; v++) {
        float4 ov;
        ov.x = acc[v * 4 + 0] * inv;
        ov.y = acc[v * 4 + 1] * inv;
        ov.z = acc[v * 4 + 2] * inv;
        ov.w = acc[v * 4 + 3] * inv;
        *(float4*)(Y + v * 4) = ov;
    }
}

// ---------------------------------------------------------------------------
extern "C" void kernel_launch(void* const* d_in, const int* in_sizes, int n_in,
                              void* d_out, int out_size)
{
    const float* x  = (const float*)d_in[0];
    const float* wq = (const float*)d_in[1];
    const float* bq = (const float*)d_in[2];
    const float* wk = (const float*)d_in[3];
    const float* bk = (const float*)d_in[4];
    const float* wv = (const float*)d_in[5];
    const float* bv = (const float*)d_in[6];
    float* y = (float*)d_out;

    conv_w_kernel<<<(3 * Hn * En + 255) / 256, 256>>>(wq, wk, wv);

    qkv_mma_kernel<<<Mn / 64, 128>>>(x, bq, bk, bv);

    const int smem_bytes = (64 * 64 + 64 * KST_LD + 64 * VS_LD + 64 * 64) * sizeof(float);
    cudaFuncSetAttribute(attn_partial_kernel, cudaFuncAttributeMaxDynamicSharedMemorySize, smem_bytes);
    attn_partial_kernel<<<dim3(MAXC, QT_N, Bn), 256, smem_bytes>>>();

    attn_combine_kernel<<<dim3(QT_N, Bn), 256>>>(y);
}

// round 6
// speedup vs baseline: 1.8673x; 1.1756x over previous
#include <cuda_runtime.h>
#include <cuda_bf16.h>
#include <cstdint>

#define Bn 8
#define Sn 2048
#define En 1024
#define Hn 64
#define Mn (Bn * Sn)
#define QT_N 32
#define CHUNK 4
#define MAXC 8

__device__ float g_q[Mn * Hn];
__device__ float g_k[Mn * Hn];
__device__ float g_v[Mn * Hn];
__device__ float g_po[(size_t)Bn * QT_N * MAXC * 64 * 64];
__device__ float g_pm[Bn * QT_N * MAXC * 64];
__device__ float g_pl[Bn * QT_N * MAXC * 64];
__device__ __nv_bfloat16 g_wt[6 * 64 * En];

__device__ __forceinline__ void mma16816(float* c, const uint32_t* a,
                                         uint32_t b0, uint32_t b1) {
    asm volatile(
        "mma.sync.aligned.m16n8k16.row.col.f32.bf16.bf16.f32 "
        "{%0,%1,%2,%3}, {%4,%5,%6,%7}, {%8,%9}, {%0,%1,%2,%3};"
        : "+f"(c[0]), "+f"(c[1]), "+f"(c[2]), "+f"(c[3])
        : "r"(a[0]), "r"(a[1]), "r"(a[2]), "r"(a[3]), "r"(b0), "r"(b1));
}
__device__ __forceinline__ uint32_t pack2bf(float f0, float f1) {
    __nv_bfloat16 b0 = __float2bfloat16(f0);
    __nv_bfloat16 b1 = __float2bfloat16(f1);
    return (uint32_t)__bfloat16_as_ushort(b0) | ((uint32_t)__bfloat16_as_ushort(b1) << 16);
}
__device__ __forceinline__ float lowf(uint32_t u)  { return __int_as_float(u << 16); }
__device__ __forceinline__ float highf(uint32_t u) { return __int_as_float(u & 0xFFFF0000u); }

// FFMA-pipe 2^x, arg in [-126, 0] after clamp; rel err ~1e-7
__device__ __forceinline__ float fexp2(float arg) {
    arg = fmaxf(arg, -120.0f);
    float t = arg + 12582912.0f;
    int iv = __float_as_int(t) - 0x4B400000;
    float f = arg - (t - 12582912.0f);
    float p = 0.00133335581f;
    p = fmaf(p, f, 0.00961804886f);
    p = fmaf(p, f, 0.0555041086f);
    p = fmaf(p, f, 0.240226506f);
    p = fmaf(p, f, 0.693147180f);
    p = fmaf(p, f, 1.0f);
    return __int_as_float(__float_as_int(p) + (iv << 23));
}
#define C2 0.1803368801111204f   // 0.125 * log2(e)

// ------------------- conv_w (unchanged) -------------------
__global__ __launch_bounds__(256) void conv_w_kernel(
    const float* __restrict__ wq, const float* __restrict__ wk, const float* __restrict__ wv)
{
    const float* wsrc[3] = {wq, wk, wv};
    int id = blockIdx.x * 256 + threadIdx.x;
    if (id >= 3 * Hn * En) return;
    int mat = id / (Hn * En);
    int rem = id % (Hn * En);
    int n = rem / En, k = rem % En;
    float v = wsrc[mat][(size_t)k * Hn + n];
    __nv_bfloat16 hi = __float2bfloat16(v);
    __nv_bfloat16 lo = __float2bfloat16(v - __bfloat162float(hi));
    g_wt[((size_t)(mat * 2 + 0) * Hn + n) * En + k] = hi;
    g_wt[((size_t)(mat * 2 + 1) * Hn + n) * En + k] = lo;
}

// ------------------- qkv (unchanged, passing) -------------------
#define KC 32
#define ALD 40
__global__ __launch_bounds__(128) void qkv_mma_kernel(
    const float* __restrict__ x,
    const float* __restrict__ bq, const float* __restrict__ bk, const float* __restrict__ bv)
{
    __shared__ __nv_bfloat16 sAh[64 * ALD];
    __shared__ __nv_bfloat16 sAl[64 * ALD];
    __shared__ __nv_bfloat16 sB[6 * 64 * ALD];
    const int t = threadIdx.x, w = t >> 5, lane = t & 31;
    const int g = lane >> 2, tt = lane & 3, m0 = blockIdx.x * 64;

    float acc[3][8][4];
#pragma unroll
    for (int m = 0; m < 3; m++)
#pragma unroll
        for (int n = 0; n < 8; n++)
#pragma unroll
            for (int i = 0; i < 4; i++) acc[m][n][i] = 0.0f;

    for (int c = 0; c < En / KC; c++) {
        const int k0 = c * KC;
        __syncthreads();
        {
            const int r = t >> 1, ks = (t & 1) * 16;
            const float* xp = x + (size_t)(m0 + r) * En + k0 + ks;
            float f[16];
#pragma unroll
            for (int j = 0; j < 4; j++) {
                float4 v4 = *(const float4*)(xp + j * 4);
                f[j*4+0]=v4.x; f[j*4+1]=v4.y; f[j*4+2]=v4.z; f[j*4+3]=v4.w;
            }
            uint32_t hi[8], lo[8];
#pragma unroll
            for (int j = 0; j < 8; j++) {
                float f0 = f[j*2], f1 = f[j*2+1];
                hi[j] = pack2bf(f0, f1);
                lo[j] = pack2bf(f0 - lowf(hi[j]), f1 - highf(hi[j]));
            }
            uint32_t eo = (uint32_t)(r * ALD + ks);
            *(uint4*)&sAh[eo]     = make_uint4(hi[0], hi[1], hi[2], hi[3]);
            *(uint4*)&sAh[eo + 8] = make_uint4(hi[4], hi[5], hi[6], hi[7]);
            *(uint4*)&sAl[eo]     = make_uint4(lo[0], lo[1], lo[2], lo[3]);
            *(uint4*)&sAl[eo + 8] = make_uint4(lo[4], lo[5], lo[6], lo[7]);
        }
#pragma unroll
        for (int rr = 0; rr < 3; rr++) {
            int r = t + rr * 128;
            const __nv_bfloat16* wp = g_wt + (size_t)r * En + k0;
            uint4 v0 = *(const uint4*)wp;
            uint4 v1 = *(const uint4*)(wp + 8);
            uint4 v2 = *(const uint4*)(wp + 16);
            uint4 v3 = *(const uint4*)(wp + 24);
            uint32_t eo = (uint32_t)(r * ALD);
            *(uint4*)&sB[eo] = v0; *(uint4*)&sB[eo+8] = v1;
            *(uint4*)&sB[eo+16] = v2; *(uint4*)&sB[eo+24] = v3;
        }
        __syncthreads();
#pragma unroll
        for (int ks = 0; ks < 2; ks++) {
            const int kb = ks * 16;
            uint32_t aH[4], aL[4];
            int r0 = (w * 16 + g) * ALD + kb + 2 * tt;
            int r1 = (w * 16 + g + 8) * ALD + kb + 2 * tt;
            aH[0] = *(const uint32_t*)&sAh[r0];
            aH[1] = *(const uint32_t*)&sAh[r1];
            aH[2] = *(const uint32_t*)&sAh[r0 + 8];
            aH[3] = *(const uint32_t*)&sAh[r1 + 8];
            aL[0] = *(const uint32_t*)&sAl[r0];
            aL[1] = *(const uint32_t*)&sAl[r1];
            aL[2] = *(const uint32_t*)&sAl[r0 + 8];
            aL[3] = *(const uint32_t*)&sAl[r1 + 8];
#pragma unroll
            for (int mat = 0; mat < 3; mat++) {
#pragma unroll
                for (int n8 = 0; n8 < 8; n8++) {
                    int bh = ((mat*2+0)*64 + n8*8 + g) * ALD + kb + 2*tt;
                    int bl = ((mat*2+1)*64 + n8*8 + g) * ALD + kb + 2*tt;
                    uint32_t bH0 = *(const uint32_t*)&sB[bh];
                    uint32_t bH1 = *(const uint32_t*)&sB[bh + 8];
                    uint32_t bL0 = *(const uint32_t*)&sB[bl];
                    uint32_t bL1 = *(const uint32_t*)&sB[bl + 8];
                    mma16816(acc[mat][n8], aH, bH0, bH1);
                    mma16816(acc[mat][n8], aH, bL0, bL1);
                    mma16816(acc[mat][n8], aL, bH0, bH1);
                }
            }
        }
    }
    float* outp[3] = {g_q, g_k, g_v};
    const float* bias[3] = {bq, bk, bv};
    const int r0 = m0 + w * 16 + g;
#pragma unroll
    for (int mat = 0; mat < 3; mat++) {
        const float* bp = bias[mat];
        float* op = outp[mat];
#pragma unroll
        for (int n8 = 0; n8 < 8; n8++) {
            int col = n8 * 8 + 2 * tt;
            float b0 = __ldg(bp + col), b1 = __ldg(bp + col + 1);
            *(float2*)(op + (size_t)r0 * Hn + col) =
                make_float2(acc[mat][n8][0] + b0, acc[mat][n8][1] + b1);
            *(float2*)(op + (size_t)(r0 + 8) * Hn + col) =
                make_float2(acc[mat][n8][2] + b0, acc[mat][n8][3] + b1);
        }
    }
}

// ------------------- attention partials on mma.sync -------------------
// smem: 6 u32 arrays [64][36]: 0:Qh 1:Ql 2:Kh 3:Kl 4:Vh(T) 5:Vl(T)
#define AR 2304
#define ATT_SMEM (6 * AR * 4)

__global__ __launch_bounds__(128) void attn_partial_kernel()
{
    const int chunk = blockIdx.x, qt = blockIdx.y, b = blockIdx.z;
    const int jt0 = chunk * CHUNK;
    if (jt0 > qt) return;
    const int jt1 = min(jt0 + CHUNK, qt + 1);

    extern __shared__ uint32_t su[];
    const int t = threadIdx.x, w = t >> 5, lane = t & 31;
    const int g = lane >> 2, tt = lane & 3;
    const int qrow = w * 16 + g;

    // stage Q: thread t -> row t>>1, 32 floats at col (t&1)*32
    {
        const float* Q = g_q + ((size_t)(b * Sn + qt * 64 + (t >> 1))) * Hn + (t & 1) * 32;
        int base = (t >> 1) * 36 + (t & 1) * 16;
#pragma unroll
        for (int v = 0; v < 4; v++) {
            float4 f0 = *(const float4*)(Q + v * 8);
            float4 f1 = *(const float4*)(Q + v * 8 + 4);
            uint32_t h0 = pack2bf(f0.x, f0.y), h1 = pack2bf(f0.z, f0.w);
            uint32_t h2 = pack2bf(f1.x, f1.y), h3 = pack2bf(f1.z, f1.w);
            uint32_t l0 = pack2bf(f0.x - lowf(h0), f0.y - highf(h0));
            uint32_t l1 = pack2bf(f0.z - lowf(h1), f0.w - highf(h1));
            uint32_t l2 = pack2bf(f1.x - lowf(h2), f1.y - highf(h2));
            uint32_t l3 = pack2bf(f1.z - lowf(h3), f1.w - highf(h3));
            *(uint4*)&su[0 * AR + base + v * 4] = make_uint4(h0, h1, h2, h3);
            *(uint4*)&su[1 * AR + base + v * 4] = make_uint4(l0, l1, l2, l3);
        }
    }
    __syncthreads();

    uint32_t aQh[4][4], aQl[4][4];
#pragma unroll
    for (int ks = 0; ks < 4; ks++) {
        int c0 = ks * 8 + tt;
        aQh[ks][0] = su[0*AR + qrow*36 + c0];
        aQh[ks][1] = su[0*AR + (qrow+8)*36 + c0];
        aQh[ks][2] = su[0*AR + qrow*36 + c0 + 4];
        aQh[ks][3] = su[0*AR + (qrow+8)*36 + c0 + 4];
        aQl[ks][0] = su[1*AR + qrow*36 + c0];
        aQl[ks][1] = su[1*AR + (qrow+8)*36 + c0];
        aQl[ks][2] = su[1*AR + qrow*36 + c0 + 4];
        aQl[ks][3] = su[1*AR + (qrow+8)*36 + c0 + 4];
    }

    float m0r = -1e30f, m1r = -1e30f, l0r = 0.0f, l1r = 0.0f;
    float O[8][4];
#pragma unroll
    for (int j = 0; j < 8; j++)
#pragma unroll
        for (int i = 0; i < 4; i++) O[j][i] = 0.0f;

    for (int jt = jt0; jt < jt1; jt++) {
        __syncthreads();
        // stage K rows
        {
            const float* K = g_k + ((size_t)(b * Sn + jt * 64 + (t >> 1))) * Hn + (t & 1) * 32;
            int base = (t >> 1) * 36 + (t & 1) * 16;
#pragma unroll
            for (int v = 0; v < 4; v++) {
                float4 f0 = *(const float4*)(K + v * 8);
                float4 f1 = *(const float4*)(K + v * 8 + 4);
                uint32_t h0 = pack2bf(f0.x, f0.y), h1 = pack2bf(f0.z, f0.w);
                uint32_t h2 = pack2bf(f1.x, f1.y), h3 = pack2bf(f1.z, f1.w);
                uint32_t l0 = pack2bf(f0.x - lowf(h0), f0.y - highf(h0));
                uint32_t l1 = pack2bf(f0.z - lowf(h1), f0.w - highf(h1));
                uint32_t l2 = pack2bf(f1.x - lowf(h2), f1.y - highf(h2));
                uint32_t l3 = pack2bf(f1.z - lowf(h3), f1.w - highf(h3));
                *(uint4*)&su[2 * AR + base + v * 4] = make_uint4(h0, h1, h2, h3);
                *(uint4*)&su[3 * AR + base + v * 4] = make_uint4(l0, l1, l2, l3);
            }
        }
        // stage V transposed: warp w handles h = w*16..w*16+15, lane = key pair
        {
            const float* V0 = g_v + ((size_t)(b * Sn + jt * 64 + 2 * lane)) * Hn + w * 16;
            const float* V1 = V0 + Hn;
#pragma unroll
            for (int v = 0; v < 4; v++) {
                float4 a4 = *(const float4*)(V0 + v * 4);
                float4 c4 = *(const float4*)(V1 + v * 4);
                float av[4] = {a4.x, a4.y, a4.z, a4.w};
                float cv[4] = {c4.x, c4.y, c4.z, c4.w};
#pragma unroll
                for (int i = 0; i < 4; i++) {
                    int h = w * 16 + v * 4 + i;
                    uint32_t hh = pack2bf(av[i], cv[i]);
                    uint32_t ll = pack2bf(av[i] - lowf(hh), cv[i] - highf(hh));
                    su[4 * AR + h * 36 + lane] = hh;
                    su[5 * AR + h * 36 + lane] = ll;
                }
            }
        }
        __syncthreads();

        // S = Q K^T
        float S[8][4];
#pragma unroll
        for (int j = 0; j < 8; j++)
#pragma unroll
            for (int i = 0; i < 4; i++) S[j][i] = 0.0f;
#pragma unroll
        for (int j = 0; j < 8; j++) {
            int kr = j * 8 + g;
#pragma unroll
            for (int ks = 0; ks < 4; ks++) {
                int c0 = ks * 8 + tt;
                uint32_t b0h = su[2*AR + kr*36 + c0];
                uint32_t b1h = su[2*AR + kr*36 + c0 + 4];
                uint32_t b0l = su[3*AR + kr*36 + c0];
                uint32_t b1l = su[3*AR + kr*36 + c0 + 4];
                mma16816(S[j], aQh[ks], b0h, b1h);
                mma16816(S[j], aQl[ks], b0h, b1h);
                mma16816(S[j], aQh[ks], b0l, b1l);
            }
        }

        if (jt == qt) {
#pragma unroll
            for (int j = 0; j < 8; j++) {
                int kc = j * 8 + 2 * tt;
                if (kc     > qrow)     S[j][0] = -1e30f;
                if (kc + 1 > qrow)     S[j][1] = -1e30f;
                if (kc     > qrow + 8) S[j][2] = -1e30f;
                if (kc + 1 > qrow + 8) S[j][3] = -1e30f;
            }
        }

        // online softmax (FFMA exp2; scale folded into C2)
        float mx0 = -1e30f, mx1 = -1e30f;
#pragma unroll
        for (int j = 0; j < 8; j++) {
            mx0 = fmaxf(mx0, fmaxf(S[j][0], S[j][1]));
            mx1 = fmaxf(mx1, fmaxf(S[j][2], S[j][3]));
        }
        mx0 = fmaxf(mx0, __shfl_xor_sync(0xffffffff, mx0, 1));
        mx0 = fmaxf(mx0, __shfl_xor_sync(0xffffffff, mx0, 2));
        mx1 = fmaxf(mx1, __shfl_xor_sync(0xffffffff, mx1, 1));
        mx1 = fmaxf(mx1, __shfl_xor_sync(0xffffffff, mx1, 2));
        float mn0 = fmaxf(m0r, mx0), mn1 = fmaxf(m1r, mx1);
        float al0 = fexp2((m0r - mn0) * C2), al1 = fexp2((m1r - mn1) * C2);
        l0r *= al0; l1r *= al1;
#pragma unroll
        for (int j = 0; j < 8; j++) {
            O[j][0] *= al0; O[j][1] *= al0; O[j][2] *= al1; O[j][3] *= al1;
        }

        uint32_t ph[4][4], pl[4][4];
        float s0 = 0.0f, s1 = 0.0f;
#pragma unroll
        for (int j = 0; j < 8; j++) {
            float p0 = fexp2((S[j][0] - mn0) * C2);
            float p1 = fexp2((S[j][1] - mn0) * C2);
            float p2 = fexp2((S[j][2] - mn1) * C2);
            float p3 = fexp2((S[j][3] - mn1) * C2);
            s0 += p0 + p1; s1 += p2 + p3;
            uint32_t h01 = pack2bf(p0, p1);
            uint32_t l01 = pack2bf(p0 - lowf(h01), p1 - highf(h01));
            uint32_t h23 = pack2bf(p2, p3);
            uint32_t l23 = pack2bf(p2 - lowf(h23), p3 - highf(h23));
            int s = j >> 1;
            if (!(j & 1)) { ph[s][0] = h01; ph[s][1] = h23; pl[s][0] = l01; pl[s][1] = l23; }
            else          { ph[s][2] = h01; ph[s][3] = h23; pl[s][2] = l01; pl[s][3] = l23; }
        }
        s0 += __shfl_xor_sync(0xffffffff, s0, 1);
        s0 += __shfl_xor_sync(0xffffffff, s0, 2);
        s1 += __shfl_xor_sync(0xffffffff, s1, 1);
        s1 += __shfl_xor_sync(0xffffffff, s1, 2);
        l0r += s0; l1r += s1;
        m0r = mn0; m1r = mn1;

        // O += P V (V transposed in smem)
#pragma unroll
        for (int j = 0; j < 8; j++) {
            int vr = j * 8 + g;
#pragma unroll
            for (int ks = 0; ks < 4; ks++) {
                int c0 = ks * 8 + tt;
                uint32_t b0h = su[4*AR + vr*36 + c0];
                uint32_t b1h = su[4*AR + vr*36 + c0 + 4];
                uint32_t b0l = su[5*AR + vr*36 + c0];
                uint32_t b1l = su[5*AR + vr*36 + c0 + 4];
                mma16816(O[j], ph[ks], b0h, b1h);
                mma16816(O[j], pl[ks], b0h, b1h);
                mma16816(O[j], ph[ks], b0l, b1l);
            }
        }
    }

    const int slot = ((b * QT_N) + qt) * MAXC + chunk;
    float* po = g_po + (size_t)slot * 64 * 64;
#pragma unroll
    for (int j = 0; j < 8; j++) {
        *(float2*)&po[qrow * 64 + j * 8 + 2 * tt]       = make_float2(O[j][0], O[j][1]);
        *(float2*)&po[(qrow + 8) * 64 + j * 8 + 2 * tt] = make_float2(O[j][2], O[j][3]);
    }
    if (tt == 0) {
        g_pm[slot * 64 + qrow]     = m0r * 0.125f;
        g_pm[slot * 64 + qrow + 8] = m1r * 0.125f;
        g_pl[slot * 64 + qrow]     = l0r;
        g_pl[slot * 64 + qrow + 8] = l1r;
    }
}

// ------------------- combine (unchanged) -------------------
__global__ __launch_bounds__(256) void attn_combine_kernel(float* __restrict__ y)
{
    const int qt = blockIdx.x, b = blockIdx.y;
    const int nc = (qt + CHUNK) / CHUNK;
    const int t = threadIdx.x, r = t >> 2, c0 = (t & 3) * 16;
    const int base = ((b * QT_N) + qt) * MAXC;

    float M = -1e30f;
#pragma unroll 4
    for (int c = 0; c < nc; c++) M = fmaxf(M, g_pm[(base + c) * 64 + r]);
    float wgt[MAXC];
    float L = 0.0f;
#pragma unroll 4
    for (int c = 0; c < nc; c++) {
        wgt[c] = __expf(g_pm[(base + c) * 64 + r] - M);
        L += g_pl[(base + c) * 64 + r] * wgt[c];
    }
    const float inv = 1.0f / L;

    float acc[16];
#pragma unroll
    for (int k = 0; k < 16; k++) acc[k] = 0.0f;
    for (int c = 0; c < nc; c++) {
        const float* po = g_po + (size_t)(base + c) * 64 * 64 + r * 64 + c0;
        const float wc = wgt[c];
#pragma unroll
        for (int v = 0; v < 4; v++) {
            float4 p4 = *(const float4*)(po + v * 4);
            acc[v*4+0] = fmaf(p4.x, wc, acc[v*4+0]);
            acc[v*4+1] = fmaf(p4.y, wc, acc[v*4+1]);
            acc[v*4+2] = fmaf(p4.z, wc, acc[v*4+2]);
            acc[v*4+3] = fmaf(p4.w, wc, acc[v*4+3]);
        }
    }
    float* Y = y + ((size_t)b * Sn + qt * 64 + r) * Hn + c0;
#pragma unroll
    for (int v = 0; v < 4; v++) {
        *(float4*)(Y + v * 4) = make_float4(acc[v*4+0]*inv, acc[v*4+1]*inv,
                                            acc[v*4+2]*inv, acc[v*4+3]*inv);
    }
}

extern "C" void kernel_launch(void* const* d_in, const int* in_sizes, int n_in,
                              void* d_out, int out_size)
{
    const float* x  = (const float*)d_in[0];
    const float* wq = (const float*)d_in[1];
    const float* bq = (const float*)d_in[2];
    const float* wk = (const float*)d_in[3];
    const float* bk = (const float*)d_in[4];
    const float* wv = (const float*)d_in[5];
    const float* bv = (const float*)d_in[6];
    float* y = (float*)d_out;

    conv_w_kernel<<<(3 * Hn * En + 255) / 256, 256>>>(wq, wk, wv);
    qkv_mma_kernel<<<Mn / 64, 128>>>(x, bq, bk, bv);

    cudaFuncSetAttribute(attn_partial_kernel, cudaFuncAttributeMaxDynamicSharedMemorySize, ATT_SMEM);
    attn_partial_kernel<<<dim3(MAXC, QT_N, Bn), 128, ATT_SMEM>>>();

    attn_combine_kernel<<<dim3(QT_N, Bn), 256>>>(y);
}

// round 7
// speedup vs baseline: 1.9572x; 1.0481x over previous
#include <cuda_runtime.h>
#include <cuda_bf16.h>
#include <cstdint>

#define Bn 8
#define Sn 2048
#define En 1024
#define Hn 64
#define Mn (Bn * Sn)
#define QT_N 16          // 128-row q tiles per batch
#define CHUNK 4
#define MAXC 8

// Packed bf16 hi/lo pairs: [row][32 u32], pair p = cols (2p,2p+1)
__device__ uint32_t g_qh[Mn * 32];
__device__ uint32_t g_ql[Mn * 32];
__device__ uint32_t g_kh[Mn * 32];
__device__ uint32_t g_kl[Mn * 32];
// V transposed: [b][h][seq-pair (1024 u32)]
__device__ uint32_t g_vth[Bn * Hn * (Sn / 2)];
__device__ uint32_t g_vtl[Bn * Hn * (Sn / 2)];

__device__ float g_po[(size_t)Bn * QT_N * MAXC * 128 * 64];
__device__ float g_pm[Bn * QT_N * MAXC * 128];
__device__ float g_pl[Bn * QT_N * MAXC * 128];
__device__ __nv_bfloat16 g_wt[6 * 64 * En];

__device__ __forceinline__ void mma16816(float* c, const uint32_t* a,
                                         uint32_t b0, uint32_t b1) {
    asm volatile(
        "mma.sync.aligned.m16n8k16.row.col.f32.bf16.bf16.f32 "
        "{%0,%1,%2,%3}, {%4,%5,%6,%7}, {%8,%9}, {%0,%1,%2,%3};"
        : "+f"(c[0]), "+f"(c[1]), "+f"(c[2]), "+f"(c[3])
        : "r"(a[0]), "r"(a[1]), "r"(a[2]), "r"(a[3]), "r"(b0), "r"(b1));
}
__device__ __forceinline__ uint32_t pack2bf(float f0, float f1) {
    __nv_bfloat16 b0 = __float2bfloat16(f0);
    __nv_bfloat16 b1 = __float2bfloat16(f1);
    return (uint32_t)__bfloat16_as_ushort(b0) | ((uint32_t)__bfloat16_as_ushort(b1) << 16);
}
__device__ __forceinline__ float lowf(uint32_t u)  { return __int_as_float(u << 16); }
__device__ __forceinline__ float highf(uint32_t u) { return __int_as_float(u & 0xFFFF0000u); }

__device__ __forceinline__ float fexp2(float arg) {
    arg = fmaxf(arg, -120.0f);
    float t = arg + 12582912.0f;
    int iv = __float_as_int(t) - 0x4B400000;
    float f = arg - (t - 12582912.0f);
    float p = 0.00133335581f;
    p = fmaf(p, f, 0.00961804886f);
    p = fmaf(p, f, 0.0555041086f);
    p = fmaf(p, f, 0.240226506f);
    p = fmaf(p, f, 0.693147180f);
    p = fmaf(p, f, 1.0f);
    return __int_as_float(__float_as_int(p) + (iv << 23));
}
#define C2 0.1803368801111204f   // 0.125 * log2(e)

// ------------------- conv_w -------------------
__global__ __launch_bounds__(256) void conv_w_kernel(
    const float* __restrict__ wq, const float* __restrict__ wk, const float* __restrict__ wv)
{
    const float* wsrc[3] = {wq, wk, wv};
    int id = blockIdx.x * 256 + threadIdx.x;
    if (id >= 3 * Hn * En) return;
    int mat = id / (Hn * En);
    int rem = id % (Hn * En);
    int n = rem / En, k = rem % En;
    float v = wsrc[mat][(size_t)k * Hn + n];
    __nv_bfloat16 hi = __float2bfloat16(v);
    __nv_bfloat16 lo = __float2bfloat16(v - __bfloat162float(hi));
    g_wt[((size_t)(mat * 2 + 0) * Hn + n) * En + k] = hi;
    g_wt[((size_t)(mat * 2 + 1) * Hn + n) * En + k] = lo;
}

// ------------------- qkv: mma.sync, packed outputs -------------------
#define KC 32
#define ALD 40
__global__ __launch_bounds__(128) void qkv_mma_kernel(
    const float* __restrict__ x,
    const float* __restrict__ bq, const float* __restrict__ bk, const float* __restrict__ bv)
{
    __shared__ char qsm[40960];
    __nv_bfloat16* sAh = (__nv_bfloat16*)qsm;              // 64*ALD
    __nv_bfloat16* sAl = (__nv_bfloat16*)(qsm + 5120);     // 64*ALD
    __nv_bfloat16* sB  = (__nv_bfloat16*)(qsm + 10240);    // 6*64*ALD
    const int t = threadIdx.x, w = t >> 5, lane = t & 31;
    const int g = lane >> 2, tt = lane & 3, m0 = blockIdx.x * 64;

    float acc[3][8][4];
#pragma unroll
    for (int m = 0; m < 3; m++)
#pragma unroll
        for (int n = 0; n < 8; n++)
#pragma unroll
            for (int i = 0; i < 4; i++) acc[m][n][i] = 0.0f;

    for (int c = 0; c < En / KC; c++) {
        const int k0 = c * KC;
        __syncthreads();
        {
            const int r = t >> 1, ks = (t & 1) * 16;
            const float* xp = x + (size_t)(m0 + r) * En + k0 + ks;
            float f[16];
#pragma unroll
            for (int j = 0; j < 4; j++) {
                float4 v4 = *(const float4*)(xp + j * 4);
                f[j*4+0]=v4.x; f[j*4+1]=v4.y; f[j*4+2]=v4.z; f[j*4+3]=v4.w;
            }
            uint32_t hi[8], lo[8];
#pragma unroll
            for (int j = 0; j < 8; j++) {
                float f0 = f[j*2], f1 = f[j*2+1];
                hi[j] = pack2bf(f0, f1);
                lo[j] = pack2bf(f0 - lowf(hi[j]), f1 - highf(hi[j]));
            }
            uint32_t eo = (uint32_t)(r * ALD + ks);
            *(uint4*)&sAh[eo]     = make_uint4(hi[0], hi[1], hi[2], hi[3]);
            *(uint4*)&sAh[eo + 8] = make_uint4(hi[4], hi[5], hi[6], hi[7]);
            *(uint4*)&sAl[eo]     = make_uint4(lo[0], lo[1], lo[2], lo[3]);
            *(uint4*)&sAl[eo + 8] = make_uint4(lo[4], lo[5], lo[6], lo[7]);
        }
#pragma unroll
        for (int rr = 0; rr < 3; rr++) {
            int r = t + rr * 128;
            const __nv_bfloat16* wp = g_wt + (size_t)r * En + k0;
            uint4 v0 = *(const uint4*)wp;
            uint4 v1 = *(const uint4*)(wp + 8);
            uint4 v2 = *(const uint4*)(wp + 16);
            uint4 v3 = *(const uint4*)(wp + 24);
            uint32_t eo = (uint32_t)(r * ALD);
            *(uint4*)&sB[eo] = v0; *(uint4*)&sB[eo+8] = v1;
            *(uint4*)&sB[eo+16] = v2; *(uint4*)&sB[eo+24] = v3;
        }
        __syncthreads();
#pragma unroll
        for (int ks = 0; ks < 2; ks++) {
            const int kb = ks * 16;
            uint32_t aH[4], aL[4];
            int r0 = (w * 16 + g) * ALD + kb + 2 * tt;
            int r1 = (w * 16 + g + 8) * ALD + kb + 2 * tt;
            aH[0] = *(const uint32_t*)&sAh[r0];
            aH[1] = *(const uint32_t*)&sAh[r1];
            aH[2] = *(const uint32_t*)&sAh[r0 + 8];
            aH[3] = *(const uint32_t*)&sAh[r1 + 8];
            aL[0] = *(const uint32_t*)&sAl[r0];
            aL[1] = *(const uint32_t*)&sAl[r1];
            aL[2] = *(const uint32_t*)&sAl[r0 + 8];
            aL[3] = *(const uint32_t*)&sAl[r1 + 8];
#pragma unroll
            for (int mat = 0; mat < 3; mat++) {
#pragma unroll
                for (int n8 = 0; n8 < 8; n8++) {
                    int bh = ((mat*2+0)*64 + n8*8 + g) * ALD + kb + 2*tt;
                    int bl = ((mat*2+1)*64 + n8*8 + g) * ALD + kb + 2*tt;
                    uint32_t bH0 = *(const uint32_t*)&sB[bh];
                    uint32_t bH1 = *(const uint32_t*)&sB[bh + 8];
                    uint32_t bL0 = *(const uint32_t*)&sB[bl];
                    uint32_t bL1 = *(const uint32_t*)&sB[bl + 8];
                    mma16816(acc[mat][n8], aH, bH0, bH1);
                    mma16816(acc[mat][n8], aH, bL0, bL1);
                    mma16816(acc[mat][n8], aL, bH0, bH1);
                }
            }
        }
    }

    // ---- epilogue: Q,K packed hi/lo ----
    const int rl = w * 16 + g;                 // local row 0..63
    {
        uint32_t* gh2[2] = {g_qh, g_kh};
        uint32_t* gl2[2] = {g_ql, g_kl};
        const float* bias2[2] = {bq, bk};
#pragma unroll
        for (int mat = 0; mat < 2; mat++) {
#pragma unroll
            for (int n8 = 0; n8 < 8; n8++) {
                int col = n8 * 8 + 2 * tt;
                float b0 = __ldg(bias2[mat] + col), b1 = __ldg(bias2[mat] + col + 1);
                float v00 = acc[mat][n8][0] + b0, v01 = acc[mat][n8][1] + b1;
                float v10 = acc[mat][n8][2] + b0, v11 = acc[mat][n8][3] + b1;
                uint32_t hA = pack2bf(v00, v01);
                uint32_t lA = pack2bf(v00 - lowf(hA), v01 - highf(hA));
                uint32_t hB = pack2bf(v10, v11);
                uint32_t lB = pack2bf(v10 - lowf(hB), v11 - highf(hB));
                size_t iA = (size_t)(m0 + rl) * 32 + n8 * 4 + tt;
                size_t iB = (size_t)(m0 + rl + 8) * 32 + n8 * 4 + tt;
                gh2[mat][iA] = hA; gl2[mat][iA] = lA;
                gh2[mat][iB] = hB; gl2[mat][iB] = lB;
            }
        }
    }
    // ---- epilogue: V transpose via smem (reuses sB region) ----
    float* vsm = (float*)(qsm + 10240);        // [64][66]
    __syncthreads();
#pragma unroll
    for (int n8 = 0; n8 < 8; n8++) {
        int col = n8 * 8 + 2 * tt;
        float b0 = __ldg(bv + col), b1 = __ldg(bv + col + 1);
        vsm[rl * 66 + col]           = acc[2][n8][0] + b0;
        vsm[rl * 66 + col + 1]       = acc[2][n8][1] + b1;
        vsm[(rl + 8) * 66 + col]     = acc[2][n8][2] + b0;
        vsm[(rl + 8) * 66 + col + 1] = acc[2][n8][3] + b1;
    }
    __syncthreads();
    {
        int h = t >> 1, half = t & 1;
        int bb = m0 >> 11;
        int sp0 = ((m0 & 2047) + half * 32) >> 1;   // seq-pair offset
        uint32_t oh[16], ol[16];
#pragma unroll
        for (int s = 0; s < 16; s++) {
            float a = vsm[(half * 32 + 2 * s) * 66 + h];
            float c = vsm[(half * 32 + 2 * s + 1) * 66 + h];
            oh[s] = pack2bf(a, c);
            ol[s] = pack2bf(a - lowf(oh[s]), c - highf(oh[s]));
        }
        uint32_t* gvh = g_vth + (size_t)(bb * Hn + h) * (Sn / 2) + sp0;
        uint32_t* gvl = g_vtl + (size_t)(bb * Hn + h) * (Sn / 2) + sp0;
#pragma unroll
        for (int q = 0; q < 4; q++) {
            *(uint4*)(gvh + q * 4) = make_uint4(oh[q*4], oh[q*4+1], oh[q*4+2], oh[q*4+3]);
            *(uint4*)(gvl + q * 4) = make_uint4(ol[q*4], ol[q*4+1], ol[q*4+2], ol[q*4+3]);
        }
    }
}

// ------------------- attention partials: 128-row q tiles -------------------
#define AR64 2304                     // 64*36 u32
#define ARQ  4608                     // 128*36 u32
#define OFF_KH (2*ARQ)
#define OFF_KL (2*ARQ + AR64)
#define OFF_VH (2*ARQ + 2*AR64)
#define OFF_VL (2*ARQ + 3*AR64)
#define ATT_SMEM ((2*ARQ + 4*AR64) * 4)   // 73728 B

__global__ __launch_bounds__(256) void attn_partial_kernel()
{
    const int chunk = blockIdx.x, qt = blockIdx.y, b = blockIdx.z;
    const int nt = 2 * qt + 2;
    const int jt0 = chunk * CHUNK;
    if (jt0 >= nt) return;
    const int jt1 = min(jt0 + CHUNK, nt);

    extern __shared__ uint32_t su[];
    const int t = threadIdx.x, w = t >> 5, lane = t & 31;
    const int g = lane >> 2, tt = lane & 3;
    const int qrow = w * 16 + g;                  // 0..127

    // stage Q hi/lo (1024 uint4 each... 128 rows x 8 uint4)
    {
        const uint4* qh4 = (const uint4*)g_qh;
        const uint4* ql4 = (const uint4*)g_ql;
        size_t gb = ((size_t)b * Sn + qt * 128) * 8;
#pragma unroll
        for (int i = 0; i < 4; i++) {
            int u = t + i * 256, r = u >> 3, c = u & 7;
            *(uint4*)&su[r * 36 + c * 4]       = qh4[gb + r * 8 + c];
            *(uint4*)&su[ARQ + r * 36 + c * 4] = ql4[gb + r * 8 + c];
        }
    }
    __syncthreads();

    uint32_t aQh[4][4], aQl[4][4];
#pragma unroll
    for (int ks = 0; ks < 4; ks++) {
        int c0 = ks * 8 + tt;
        aQh[ks][0] = su[qrow*36 + c0];
        aQh[ks][1] = su[(qrow+8)*36 + c0];
        aQh[ks][2] = su[qrow*36 + c0 + 4];
        aQh[ks][3] = su[(qrow+8)*36 + c0 + 4];
        aQl[ks][0] = su[ARQ + qrow*36 + c0];
        aQl[ks][1] = su[ARQ + (qrow+8)*36 + c0];
        aQl[ks][2] = su[ARQ + qrow*36 + c0 + 4];
        aQl[ks][3] = su[ARQ + (qrow+8)*36 + c0 + 4];
    }

    float m0r = -1e30f, m1r = -1e30f, l0r = 0.0f, l1r = 0.0f;
    float O[8][4];
#pragma unroll
    for (int j = 0; j < 8; j++)
#pragma unroll
        for (int i = 0; i < 4; i++) O[j][i] = 0.0f;

    for (int jt = jt0; jt < jt1; jt++) {
        __syncthreads();
        {
            const uint4* kh4 = (const uint4*)g_kh;
            const uint4* kl4 = (const uint4*)g_kl;
            const uint4* vh4 = (const uint4*)g_vth;
            const uint4* vl4 = (const uint4*)g_vtl;
            size_t kb = ((size_t)b * Sn + jt * 64) * 8;
#pragma unroll
            for (int i = 0; i < 2; i++) {
                int u = t + i * 256, r = u >> 3, c = u & 7;
                *(uint4*)&su[OFF_KH + r * 36 + c * 4] = kh4[kb + r * 8 + c];
                *(uint4*)&su[OFF_KL + r * 36 + c * 4] = kl4[kb + r * 8 + c];
                size_t vb = (size_t)(b * Hn + r) * 256 + jt * 8 + c;
                *(uint4*)&su[OFF_VH + r * 36 + c * 4] = vh4[vb];
                *(uint4*)&su[OFF_VL + r * 36 + c * 4] = vl4[vb];
            }
        }
        __syncthreads();

        float S[8][4];
#pragma unroll
        for (int j = 0; j < 8; j++)
#pragma unroll
            for (int i = 0; i < 4; i++) S[j][i] = 0.0f;
#pragma unroll
        for (int j = 0; j < 8; j++) {
            int kr = j * 8 + g;
#pragma unroll
            for (int ks = 0; ks < 4; ks++) {
                int c0 = ks * 8 + tt;
                uint32_t b0h = su[OFF_KH + kr*36 + c0];
                uint32_t b1h = su[OFF_KH + kr*36 + c0 + 4];
                uint32_t b0l = su[OFF_KL + kr*36 + c0];
                uint32_t b1l = su[OFF_KL + kr*36 + c0 + 4];
                mma16816(S[j], aQh[ks], b0h, b1h);
                mma16816(S[j], aQl[ks], b0h, b1h);
                mma16816(S[j], aQh[ks], b0l, b1l);
            }
        }

        if (jt >= 2 * qt) {
            int qg0 = qt * 128 + qrow, qg1 = qg0 + 8;
            int kbse = jt * 64;
#pragma unroll
            for (int j = 0; j < 8; j++) {
                int kc = kbse + j * 8 + 2 * tt;
                if (kc     > qg0) S[j][0] = -1e30f;
                if (kc + 1 > qg0) S[j][1] = -1e30f;
                if (kc     > qg1) S[j][2] = -1e30f;
                if (kc + 1 > qg1) S[j][3] = -1e30f;
            }
        }

        float mx0 = -1e30f, mx1 = -1e30f;
#pragma unroll
        for (int j = 0; j < 8; j++) {
            mx0 = fmaxf(mx0, fmaxf(S[j][0], S[j][1]));
            mx1 = fmaxf(mx1, fmaxf(S[j][2], S[j][3]));
        }
        mx0 = fmaxf(mx0, __shfl_xor_sync(0xffffffff, mx0, 1));
        mx0 = fmaxf(mx0, __shfl_xor_sync(0xffffffff, mx0, 2));
        mx1 = fmaxf(mx1, __shfl_xor_sync(0xffffffff, mx1, 1));
        mx1 = fmaxf(mx1, __shfl_xor_sync(0xffffffff, mx1, 2));
        float mn0 = fmaxf(m0r, mx0), mn1 = fmaxf(m1r, mx1);
        float al0 = fexp2((m0r - mn0) * C2), al1 = fexp2((m1r - mn1) * C2);
        l0r *= al0; l1r *= al1;
#pragma unroll
        for (int j = 0; j < 8; j++) {
            O[j][0] *= al0; O[j][1] *= al0; O[j][2] *= al1; O[j][3] *= al1;
        }

        uint32_t ph[4][4], pl[4][4];
        float s0 = 0.0f, s1 = 0.0f;
#pragma unroll
        for (int j = 0; j < 8; j++) {
            float p0 = fexp2((S[j][0] - mn0) * C2);
            float p1 = fexp2((S[j][1] - mn0) * C2);
            float p2 = fexp2((S[j][2] - mn1) * C2);
            float p3 = fexp2((S[j][3] - mn1) * C2);
            s0 += p0 + p1; s1 += p2 + p3;
            uint32_t h01 = pack2bf(p0, p1);
            uint32_t l01 = pack2bf(p0 - lowf(h01), p1 - highf(h01));
            uint32_t h23 = pack2bf(p2, p3);
            uint32_t l23 = pack2bf(p2 - lowf(h23), p3 - highf(h23));
            int s = j >> 1;
            if (!(j & 1)) { ph[s][0] = h01; ph[s][1] = h23; pl[s][0] = l01; pl[s][1] = l23; }
            else          { ph[s][2] = h01; ph[s][3] = h23; pl[s][2] = l01; pl[s][3] = l23; }
        }
        s0 += __shfl_xor_sync(0xffffffff, s0, 1);
        s0 += __shfl_xor_sync(0xffffffff, s0, 2);
        s1 += __shfl_xor_sync(0xffffffff, s1, 1);
        s1 += __shfl_xor_sync(0xffffffff, s1, 2);
        l0r += s0; l1r += s1;
        m0r = mn0; m1r = mn1;

#pragma unroll
        for (int j = 0; j < 8; j++) {
            int vr = j * 8 + g;
#pragma unroll
            for (int ks = 0; ks < 4; ks++) {
                int c0 = ks * 8 + tt;
                uint32_t b0h = su[OFF_VH + vr*36 + c0];
                uint32_t b1h = su[OFF_VH + vr*36 + c0 + 4];
                uint32_t b0l = su[OFF_VL + vr*36 + c0];
                uint32_t b1l = su[OFF_VL + vr*36 + c0 + 4];
                mma16816(O[j], ph[ks], b0h, b1h);
                mma16816(O[j], pl[ks], b0h, b1h);
                mma16816(O[j], ph[ks], b0l, b1l);
            }
        }
    }

    const int slot = ((b * QT_N) + qt) * MAXC + chunk;
    float* po = g_po + (size_t)slot * 128 * 64;
#pragma unroll
    for (int j = 0; j < 8; j++) {
        *(float2*)&po[qrow * 64 + j * 8 + 2 * tt]       = make_float2(O[j][0], O[j][1]);
        *(float2*)&po[(qrow + 8) * 64 + j * 8 + 2 * tt] = make_float2(O[j][2], O[j][3]);
    }
    if (tt == 0) {
        g_pm[slot * 128 + qrow]     = m0r * 0.125f;
        g_pm[slot * 128 + qrow + 8] = m1r * 0.125f;
        g_pl[slot * 128 + qrow]     = l0r;
        g_pl[slot * 128 + qrow + 8] = l1r;
    }
}

// ------------------- combine -------------------
__global__ __launch_bounds__(256) void attn_combine_kernel(float* __restrict__ y)
{
    const int qt = blockIdx.x >> 1, half = blockIdx.x & 1, b = blockIdx.y;
    const int nc = min((2 * qt + 2 + CHUNK - 1) / CHUNK, MAXC);
    const int t = threadIdx.x;
    const int r = half * 64 + (t >> 2), c0 = (t & 3) * 16;
    const int base = ((b * QT_N) + qt) * MAXC;

    float M = -1e30f;
#pragma unroll 4
    for (int c = 0; c < nc; c++) M = fmaxf(M, g_pm[(base + c) * 128 + r]);
    float wgt[MAXC];
    float L = 0.0f;
#pragma unroll 4
    for (int c = 0; c < nc; c++) {
        wgt[c] = __expf(g_pm[(base + c) * 128 + r] - M);
        L += g_pl[(base + c) * 128 + r] * wgt[c];
    }
    const float inv = 1.0f / L;

    float acc[16];
#pragma unroll
    for (int k = 0; k < 16; k++) acc[k] = 0.0f;
    for (int c = 0; c < nc; c++) {
        const float* po = g_po + (size_t)(base + c) * 128 * 64 + r * 64 + c0;
        const float wc = wgt[c];
#pragma unroll
        for (int v = 0; v < 4; v++) {
            float4 p4 = *(const float4*)(po + v * 4);
            acc[v*4+0] = fmaf(p4.x, wc, acc[v*4+0]);
            acc[v*4+1] = fmaf(p4.y, wc, acc[v*4+1]);
            acc[v*4+2] = fmaf(p4.z, wc, acc[v*4+2]);
            acc[v*4+3] = fmaf(p4.w, wc, acc[v*4+3]);
        }
    }
    float* Y = y + ((size_t)b * Sn + qt * 128 + r) * Hn + c0;
#pragma unroll
    for (int v = 0; v < 4; v++) {
        *(float4*)(Y + v * 4) = make_float4(acc[v*4+0]*inv, acc[v*4+1]*inv,
                                            acc[v*4+2]*inv, acc[v*4+3]*inv);
    }
}

extern "C" void kernel_launch(void* const* d_in, const int* in_sizes, int n_in,
                              void* d_out, int out_size)
{
    const float* x  = (const float*)d_in[0];
    const float* wq = (const float*)d_in[1];
    const float* bq = (const float*)d_in[2];
    const float* wk = (const float*)d_in[3];
    const float* bk = (const float*)d_in[4];
    const float* wv = (const float*)d_in[5];
    const float* bv = (const float*)d_in[6];
    float* y = (float*)d_out;

    conv_w_kernel<<<(3 * Hn * En + 255) / 256, 256>>>(wq, wk, wv);
    qkv_mma_kernel<<<Mn / 64, 128>>>(x, bq, bk, bv);

    cudaFuncSetAttribute(attn_partial_kernel, cudaFuncAttributeMaxDynamicSharedMemorySize, ATT_SMEM);
    attn_partial_kernel<<<dim3(MAXC, QT_N, Bn), 256, ATT_SMEM>>>();

    attn_combine_kernel<<<dim3(2 * QT_N, Bn), 256>>>(y);
}

// round 9
// speedup vs baseline: 2.1083x; 1.0772x over previous
#include <cuda_runtime.h>
#include <cuda_bf16.h>
#include <cstdint>

#define Bn 8
#define Sn 2048
#define En 1024
#define Hn 64
#define Mn (Bn * Sn)
#define QT_N 16
#define CHUNK 4
#define MAXC 8

__device__ uint32_t g_qh[Mn * 32];
__device__ uint32_t g_ql[Mn * 32];
__device__ uint32_t g_kh[Mn * 32];
__device__ uint32_t g_kl[Mn * 32];
__device__ uint32_t g_vth[Bn * Hn * (Sn / 2)];
__device__ uint32_t g_vtl[Bn * Hn * (Sn / 2)];

__device__ float g_po[(size_t)Bn * QT_N * MAXC * 128 * 64];
__device__ float g_pm[Bn * QT_N * MAXC * 128];
__device__ float g_pl[Bn * QT_N * MAXC * 128];
__device__ __nv_bfloat16 g_wt[6 * 64 * En];

__device__ __forceinline__ uint32_t smem_u32(const void* p) {
    uint32_t a;
    asm("{ .reg .u64 t; cvta.to.shared.u64 t, %1; cvt.u32.u64 %0, t; }" : "=r"(a) : "l"(p));
    return a;
}
__device__ __forceinline__ void mma16816(float* c, const uint32_t* a,
                                         uint32_t b0, uint32_t b1) {
    asm volatile(
        "mma.sync.aligned.m16n8k16.row.col.f32.bf16.bf16.f32 "
        "{%0,%1,%2,%3}, {%4,%5,%6,%7}, {%8,%9}, {%0,%1,%2,%3};"
        : "+f"(c[0]), "+f"(c[1]), "+f"(c[2]), "+f"(c[3])
        : "r"(a[0]), "r"(a[1]), "r"(a[2]), "r"(a[3]), "r"(b0), "r"(b1));
}
#define LDMX4(r, ad) \
    asm volatile("ldmatrix.sync.aligned.m8n8.x4.shared.b16 {%0,%1,%2,%3}, [%4];" \
        : "=r"((r)[0]), "=r"((r)[1]), "=r"((r)[2]), "=r"((r)[3]) : "r"(ad))

__device__ __forceinline__ uint32_t pack2bf(float f0, float f1) {
    __nv_bfloat16 b0 = __float2bfloat16(f0);
    __nv_bfloat16 b1 = __float2bfloat16(f1);
    return (uint32_t)__bfloat16_as_ushort(b0) | ((uint32_t)__bfloat16_as_ushort(b1) << 16);
}
__device__ __forceinline__ float lowf(uint32_t u)  { return __int_as_float(u << 16); }
__device__ __forceinline__ float highf(uint32_t u) { return __int_as_float(u & 0xFFFF0000u); }

__device__ __forceinline__ float fexp2(float arg) {
    arg = fmaxf(arg, -120.0f);
    float t = arg + 12582912.0f;
    int iv = __float_as_int(t) - 0x4B400000;
    float f = arg - (t - 12582912.0f);
    float p = 0.00133335581f;
    p = fmaf(p, f, 0.00961804886f);
    p = fmaf(p, f, 0.0555041086f);
    p = fmaf(p, f, 0.240226506f);
    p = fmaf(p, f, 0.693147180f);
    p = fmaf(p, f, 1.0f);
    return __int_as_float(__float_as_int(p) + (iv << 23));
}
#define C2 0.1803368801111204f

// ------------------- conv_w -------------------
__global__ __launch_bounds__(256) void conv_w_kernel(
    const float* __restrict__ wq, const float* __restrict__ wk, const float* __restrict__ wv)
{
    const float* wsrc[3] = {wq, wk, wv};
    int id = blockIdx.x * 256 + threadIdx.x;
    if (id >= 3 * Hn * En) return;
    int mat = id / (Hn * En);
    int rem = id % (Hn * En);
    int n = rem / En, k = rem % En;
    float v = wsrc[mat][(size_t)k * Hn + n];
    __nv_bfloat16 hi = __float2bfloat16(v);
    __nv_bfloat16 lo = __float2bfloat16(v - __bfloat162float(hi));
    g_wt[((size_t)(mat * 2 + 0) * Hn + n) * En + k] = hi;
    g_wt[((size_t)(mat * 2 + 1) * Hn + n) * En + k] = lo;
}

// ------------------- qkv: mma.sync + ldmatrix -------------------
#define KC 32
#define ALD 40
__global__ __launch_bounds__(128) void qkv_mma_kernel(
    const float* __restrict__ x,
    const float* __restrict__ bq, const float* __restrict__ bk, const float* __restrict__ bv)
{
    __shared__ char qsm[40960];
    __nv_bfloat16* sAh = (__nv_bfloat16*)qsm;
    __nv_bfloat16* sAl = (__nv_bfloat16*)(qsm + 5120);
    __nv_bfloat16* sB  = (__nv_bfloat16*)(qsm + 10240);
    const int t = threadIdx.x, w = t >> 5, lane = t & 31;
    const int g = lane >> 2, tt = lane & 3, m0 = blockIdx.x * 64;

    float acc[3][8][4];
#pragma unroll
    for (int m = 0; m < 3; m++)
#pragma unroll
        for (int n = 0; n < 8; n++)
#pragma unroll
            for (int i = 0; i < 4; i++) acc[m][n][i] = 0.0f;

    const int arow = w * 16 + (lane & 15);
    const int acol = (lane >> 4) << 3;
    const int brow = lane & 7;
    const int bcol = ((lane >> 3) & 3) << 3;

    for (int c = 0; c < En / KC; c++) {
        const int k0 = c * KC;
        __syncthreads();
        {
            const int r = t >> 1, ks = (t & 1) * 16;
            const float* xp = x + (size_t)(m0 + r) * En + k0 + ks;
            float f[16];
#pragma unroll
            for (int j = 0; j < 4; j++) {
                float4 v4 = *(const float4*)(xp + j * 4);
                f[j*4+0]=v4.x; f[j*4+1]=v4.y; f[j*4+2]=v4.z; f[j*4+3]=v4.w;
            }
            uint32_t hi[8], lo[8];
#pragma unroll
            for (int j = 0; j < 8; j++) {
                float f0 = f[j*2], f1 = f[j*2+1];
                hi[j] = pack2bf(f0, f1);
                lo[j] = pack2bf(f0 - lowf(hi[j]), f1 - highf(hi[j]));
            }
            uint32_t eo = (uint32_t)(r * ALD + ks);
            *(uint4*)&sAh[eo]     = make_uint4(hi[0], hi[1], hi[2], hi[3]);
            *(uint4*)&sAh[eo + 8] = make_uint4(hi[4], hi[5], hi[6], hi[7]);
            *(uint4*)&sAl[eo]     = make_uint4(lo[0], lo[1], lo[2], lo[3]);
            *(uint4*)&sAl[eo + 8] = make_uint4(lo[4], lo[5], lo[6], lo[7]);
        }
#pragma unroll
        for (int rr = 0; rr < 3; rr++) {
            int r = t + rr * 128;
            const __nv_bfloat16* wp = g_wt + (size_t)r * En + k0;
            uint4 v0 = *(const uint4*)wp;
            uint4 v1 = *(const uint4*)(wp + 8);
            uint4 v2 = *(const uint4*)(wp + 16);
            uint4 v3 = *(const uint4*)(wp + 24);
            uint32_t eo = (uint32_t)(r * ALD);
            *(uint4*)&sB[eo] = v0; *(uint4*)&sB[eo+8] = v1;
            *(uint4*)&sB[eo+16] = v2; *(uint4*)&sB[eo+24] = v3;
        }
        __syncthreads();

        uint32_t aH[2][4], aL[2][4];
#pragma unroll
        for (int ks = 0; ks < 2; ks++) {
            uint32_t adh = smem_u32(&sAh[arow * ALD + ks * 16 + acol]);
            uint32_t adl = smem_u32(&sAl[arow * ALD + ks * 16 + acol]);
            LDMX4(aH[ks], adh);
            LDMX4(aL[ks], adl);
        }
#pragma unroll
        for (int mat = 0; mat < 3; mat++) {
#pragma unroll
            for (int n8 = 0; n8 < 8; n8++) {
                uint32_t bh[4], bl[4];
                uint32_t adh = smem_u32(&sB[((mat*2+0)*64 + n8*8 + brow) * ALD + bcol]);
                uint32_t adl = smem_u32(&sB[((mat*2+1)*64 + n8*8 + brow) * ALD + bcol]);
                LDMX4(bh, adh);
                LDMX4(bl, adl);
                mma16816(acc[mat][n8], aH[0], bh[0], bh[1]);
                mma16816(acc[mat][n8], aL[0], bh[0], bh[1]);
                mma16816(acc[mat][n8], aH[0], bl[0], bl[1]);
                mma16816(acc[mat][n8], aH[1], bh[2], bh[3]);
                mma16816(acc[mat][n8], aL[1], bh[2], bh[3]);
                mma16816(acc[mat][n8], aH[1], bl[2], bl[3]);
            }
        }
    }

    // ---- epilogue: Q,K packed hi/lo ----
    const int rl = w * 16 + g;
    {
        uint32_t* gh2[2] = {g_qh, g_kh};
        uint32_t* gl2[2] = {g_ql, g_kl};
        const float* bias2[2] = {bq, bk};
#pragma unroll
        for (int mat = 0; mat < 2; mat++) {
#pragma unroll
            for (int n8 = 0; n8 < 8; n8++) {
                int col = n8 * 8 + 2 * tt;
                float b0 = __ldg(bias2[mat] + col), b1 = __ldg(bias2[mat] + col + 1);
                float v00 = acc[mat][n8][0] + b0, v01 = acc[mat][n8][1] + b1;
                float v10 = acc[mat][n8][2] + b0, v11 = acc[mat][n8][3] + b1;
                uint32_t hA = pack2bf(v00, v01);
                uint32_t lA = pack2bf(v00 - lowf(hA), v01 - highf(hA));
                uint32_t hB = pack2bf(v10, v11);
                uint32_t lB = pack2bf(v10 - lowf(hB), v11 - highf(hB));
                size_t iA = (size_t)(m0 + rl) * 32 + n8 * 4 + tt;
                size_t iB = (size_t)(m0 + rl + 8) * 32 + n8 * 4 + tt;
                gh2[mat][iA] = hA; gl2[mat][iA] = lA;
                gh2[mat][iB] = hB; gl2[mat][iB] = lB;
            }
        }
    }
    // ---- epilogue: V transpose via smem ----
    float* vsm = (float*)(qsm + 10240);
    __syncthreads();
#pragma unroll
    for (int n8 = 0; n8 < 8; n8++) {
        int col = n8 * 8 + 2 * tt;
        float b0 = __ldg(bv + col), b1 = __ldg(bv + col + 1);
        vsm[rl * 66 + col]           = acc[2][n8][0] + b0;
        vsm[rl * 66 + col + 1]       = acc[2][n8][1] + b1;
        vsm[(rl + 8) * 66 + col]     = acc[2][n8][2] + b0;
        vsm[(rl + 8) * 66 + col + 1] = acc[2][n8][3] + b1;
    }
    __syncthreads();
    {
        int h = t >> 1, half = t & 1;
        int bb = m0 >> 11;
        int sp0 = ((m0 & 2047) + half * 32) >> 1;
        uint32_t oh[16], ol[16];
#pragma unroll
        for (int s = 0; s < 16; s++) {
            float a = vsm[(half * 32 + 2 * s) * 66 + h];
            float c = vsm[(half * 32 + 2 * s + 1) * 66 + h];
            oh[s] = pack2bf(a, c);
            ol[s] = pack2bf(a - lowf(oh[s]), c - highf(oh[s]));
        }
        uint32_t* gvh = g_vth + (size_t)(bb * Hn + h) * (Sn / 2) + sp0;
        uint32_t* gvl = g_vtl + (size_t)(bb * Hn + h) * (Sn / 2) + sp0;
#pragma unroll
        for (int q = 0; q < 4; q++) {
            *(uint4*)(gvh + q * 4) = make_uint4(oh[q*4], oh[q*4+1], oh[q*4+2], oh[q*4+3]);
            *(uint4*)(gvl + q * 4) = make_uint4(ol[q*4], ol[q*4+1], ol[q*4+2], ol[q*4+3]);
        }
    }
}

// ------------------- attention partials -------------------
#define AR64 2304
#define ARQ  4608
#define OFF_KH (2*ARQ)
#define OFF_KL (2*ARQ + AR64)
#define OFF_VH (2*ARQ + 2*AR64)
#define OFF_VL (2*ARQ + 3*AR64)
#define ATT_SMEM ((2*ARQ + 4*AR64) * 4)

__global__ __launch_bounds__(256) void attn_partial_kernel()
{
    const int chunk = blockIdx.x, qt = blockIdx.y, b = blockIdx.z;
    const int nt = 2 * qt + 2;
    const int jt0 = chunk * CHUNK;
    if (jt0 >= nt) return;
    const int jt1 = min(jt0 + CHUNK, nt);

    extern __shared__ uint32_t su[];
    const uint32_t sbase = smem_u32(su);
    const int t = threadIdx.x, w = t >> 5, lane = t & 31;
    const int g = lane >> 2, tt = lane & 3;
    const int qrow = w * 16 + g;

    const int arow = w * 16 + (lane & 15);
    const int acolB = ((lane >> 4) << 3) * 2;
    const int brow = lane & 7;
    const int bcolB = (((lane >> 3) & 3) << 3) * 2;

    {
        const uint4* qh4 = (const uint4*)g_qh;
        const uint4* ql4 = (const uint4*)g_ql;
        size_t gb = ((size_t)b * Sn + qt * 128) * 8;
#pragma unroll
        for (int i = 0; i < 4; i++) {
            int u = t + i * 256, r = u >> 3, c = u & 7;
            *(uint4*)&su[r * 36 + c * 4]       = qh4[gb + r * 8 + c];
            *(uint4*)&su[ARQ + r * 36 + c * 4] = ql4[gb + r * 8 + c];
        }
    }
    __syncthreads();

    uint32_t aQh[4][4], aQl[4][4];
#pragma unroll
    for (int ks = 0; ks < 4; ks++) {
        uint32_t ad = sbase + arow * 144 + ks * 32 + acolB;
        LDMX4(aQh[ks], ad);
        LDMX4(aQl[ks], ad + ARQ * 4);
    }

    float m0r = -1e30f, m1r = -1e30f, l0r = 0.0f, l1r = 0.0f;
    float O[8][4];
#pragma unroll
    for (int j = 0; j < 8; j++)
#pragma unroll
        for (int i = 0; i < 4; i++) O[j][i] = 0.0f;

    for (int jt = jt0; jt < jt1; jt++) {
        __syncthreads();
        {
            const uint4* kh4 = (const uint4*)g_kh;
            const uint4* kl4 = (const uint4*)g_kl;
            const uint4* vh4 = (const uint4*)g_vth;
            const uint4* vl4 = (const uint4*)g_vtl;
            size_t kb = ((size_t)b * Sn + jt * 64) * 8;
#pragma unroll
            for (int i = 0; i < 2; i++) {
                int u = t + i * 256, r = u >> 3, c = u & 7;
                *(uint4*)&su[OFF_KH + r * 36 + c * 4] = kh4[kb + r * 8 + c];
                *(uint4*)&su[OFF_KL + r * 36 + c * 4] = kl4[kb + r * 8 + c];
                size_t vb = (size_t)(b * Hn + r) * 256 + jt * 8 + c;
                *(uint4*)&su[OFF_VH + r * 36 + c * 4] = vh4[vb];
                *(uint4*)&su[OFF_VL + r * 36 + c * 4] = vl4[vb];
            }
        }
        __syncthreads();

        float S[8][4];
#pragma unroll
        for (int j = 0; j < 8; j++)
#pragma unroll
            for (int i = 0; i < 4; i++) S[j][i] = 0.0f;
#pragma unroll
        for (int j = 0; j < 8; j++) {
            uint32_t adh = sbase + (OFF_KH + (j * 8 + brow) * 36) * 4 + bcolB;
            uint32_t adl = sbase + (OFF_KL + (j * 8 + brow) * 36) * 4 + bcolB;
            uint32_t kh[4], kl[4], kh2[4], kl2[4];
            LDMX4(kh, adh);
            LDMX4(kl, adl);
            LDMX4(kh2, adh + 64);
            LDMX4(kl2, adl + 64);
            mma16816(S[j], aQh[0], kh[0], kh[1]);
            mma16816(S[j], aQl[0], kh[0], kh[1]);
            mma16816(S[j], aQh[0], kl[0], kl[1]);
            mma16816(S[j], aQh[1], kh[2], kh[3]);
            mma16816(S[j], aQl[1], kh[2], kh[3]);
            mma16816(S[j], aQh[1], kl[2], kl[3]);
            mma16816(S[j], aQh[2], kh2[0], kh2[1]);
            mma16816(S[j], aQl[2], kh2[0], kh2[1]);
            mma16816(S[j], aQh[2], kl2[0], kl2[1]);
            mma16816(S[j], aQh[3], kh2[2], kh2[3]);
            mma16816(S[j], aQl[3], kh2[2], kh2[3]);
            mma16816(S[j], aQh[3], kl2[2], kl2[3]);
        }

        if (jt >= 2 * qt) {
            int qg0 = qt * 128 + qrow, qg1 = qg0 + 8;
            int kbse = jt * 64;
#pragma unroll
            for (int j = 0; j < 8; j++) {
                int kc = kbse + j * 8 + 2 * tt;
                if (kc     > qg0) S[j][0] = -1e30f;
                if (kc + 1 > qg0) S[j][1] = -1e30f;
                if (kc     > qg1) S[j][2] = -1e30f;
                if (kc + 1 > qg1) S[j][3] = -1e30f;
            }
        }

        float mx0 = -1e30f, mx1 = -1e30f;
#pragma unroll
        for (int j = 0; j < 8; j++) {
            mx0 = fmaxf(mx0, fmaxf(S[j][0], S[j][1]));
            mx1 = fmaxf(mx1, fmaxf(S[j][2], S[j][3]));
        }
        mx0 = fmaxf(mx0, __shfl_xor_sync(0xffffffff, mx0, 1));
        mx0 = fmaxf(mx0, __shfl_xor_sync(0xffffffff, mx0, 2));
        mx1 = fmaxf(mx1, __shfl_xor_sync(0xffffffff, mx1, 1));
        mx1 = fmaxf(mx1, __shfl_xor_sync(0xffffffff, mx1, 2));
        float mn0 = fmaxf(m0r, mx0), mn1 = fmaxf(m1r, mx1);
        float al0 = fexp2((m0r - mn0) * C2), al1 = fexp2((m1r - mn1) * C2);
        l0r *= al0; l1r *= al1;
#pragma unroll
        for (int j = 0; j < 8; j++) {
            O[j][0] *= al0; O[j][1] *= al0; O[j][2] *= al1; O[j][3] *= al1;
        }

        uint32_t ph[4][4], pl[4][4];
        float s0 = 0.0f, s1 = 0.0f;
#pragma unroll
        for (int j = 0; j < 8; j++) {
            float p0 = fexp2((S[j][0] - mn0) * C2);
            float p1 = fexp2((S[j][1] - mn0) * C2);
            float p2 = fexp2((S[j][2] - mn1) * C2);
            float p3 = fexp2((S[j][3] - mn1) * C2);
            s0 += p0 + p1; s1 += p2 + p3;
            uint32_t h01 = pack2bf(p0, p1);
            uint32_t l01 = pack2bf(p0 - lowf(h01), p1 - highf(h01));
            uint32_t h23 = pack2bf(p2, p3);
            uint32_t l23 = pack2bf(p2 - lowf(h23), p3 - highf(h23));
            int s = j >> 1;
            if (!(j & 1)) { ph[s][0] = h01; ph[s][1] = h23; pl[s][0] = l01; pl[s][1] = l23; }
            else          { ph[s][2] = h01; ph[s][3] = h23; pl[s][2] = l01; pl[s][3] = l23; }
        }
        s0 += __shfl_xor_sync(0xffffffff, s0, 1);
        s0 += __shfl_xor_sync(0xffffffff, s0, 2);
        s1 += __shfl_xor_sync(0xffffffff, s1, 1);
        s1 += __shfl_xor_sync(0xffffffff, s1, 2);
        l0r += s0; l1r += s1;
        m0r = mn0; m1r = mn1;

#pragma unroll
        for (int j = 0; j < 8; j++) {
            uint32_t adh = sbase + (OFF_VH + (j * 8 + brow) * 36) * 4 + bcolB;
            uint32_t adl = sbase + (OFF_VL + (j * 8 + brow) * 36) * 4 + bcolB;
            uint32_t vh[4], vl[4], vh2[4], vl2[4];
            LDMX4(vh, adh);
            LDMX4(vl, adl);
            LDMX4(vh2, adh + 64);
            LDMX4(vl2, adl + 64);
            mma16816(O[j], ph[0], vh[0], vh[1]);
            mma16816(O[j], pl[0], vh[0], vh[1]);
            mma16816(O[j], ph[0], vl[0], vl[1]);
            mma16816(O[j], ph[1], vh[2], vh[3]);
            mma16816(O[j], pl[1], vh[2], vh[3]);
            mma16816(O[j], ph[1], vl[2], vl[3]);
            mma16816(O[j], ph[2], vh2[0], vh2[1]);
            mma16816(O[j], pl[2], vh2[0], vh2[1]);
            mma16816(O[j], ph[2], vl2[0], vl2[1]);
            mma16816(O[j], ph[3], vh2[2], vh2[3]);
            mma16816(O[j], pl[3], vh2[2], vh2[3]);
            mma16816(O[j], ph[3], vl2[2], vl2[3]);
        }
    }

    const int slot = ((b * QT_N) + qt) * MAXC + chunk;
    float* po = g_po + (size_t)slot * 128 * 64;
#pragma unroll
    for (int j = 0; j < 8; j++) {
        *(float2*)&po[qrow * 64 + j * 8 + 2 * tt]       = make_float2(O[j][0], O[j][1]);
        *(float2*)&po[(qrow + 8) * 64 + j * 8 + 2 * tt] = make_float2(O[j][2], O[j][3]);
    }
    if (tt == 0) {
        g_pm[slot * 128 + qrow]     = m0r * 0.125f;
        g_pm[slot * 128 + qrow + 8] = m1r * 0.125f;
        g_pl[slot * 128 + qrow]     = l0r;
        g_pl[slot * 128 + qrow + 8] = l1r;
    }
}

// ------------------- combine -------------------
__global__ __launch_bounds__(256) void attn_combine_kernel(float* __restrict__ y)
{
    const int qt = blockIdx.x >> 1, half = blockIdx.x & 1, b = blockIdx.y;
    const int nc = min((2 * qt + 2 + CHUNK - 1) / CHUNK, MAXC);
    const int t = threadIdx.x;
    const int r = half * 64 + (t >> 2), c0 = (t & 3) * 16;
    const int base = ((b * QT_N) + qt) * MAXC;

    float M = -1e30f;
#pragma unroll 4
    for (int c = 0; c < nc; c++) M = fmaxf(M, g_pm[(base + c) * 128 + r]);
    float wgt[MAXC];
    float L = 0.0f;
#pragma unroll 4
    for (int c = 0; c < nc; c++) {
        wgt[c] = __expf(g_pm[(base + c) * 128 + r] - M);
        L += g_pl[(base + c) * 128 + r] * wgt[c];
    }
    const float inv = 1.0f / L;

    float acc[16];
#pragma unroll
    for (int k = 0; k < 16; k++) acc[k] = 0.0f;
    for (int c = 0; c < nc; c++) {
        const float* po = g_po + (size_t)(base + c) * 128 * 64 + r * 64 + c0;
        const float wc = wgt[c];
#pragma unroll
        for (int v = 0; v < 4; v++) {
            float4 p4 = *(const float4*)(po + v * 4);
            acc[v*4+0] = fmaf(p4.x, wc, acc[v*4+0]);
            acc[v*4+1] = fmaf(p4.y, wc, acc[v*4+1]);
            acc[v*4+2] = fmaf(p4.z, wc, acc[v*4+2]);
            acc[v*4+3] = fmaf(p4.w, wc, acc[v*4+3]);
        }
    }
    float* Y = y + ((size_t)b * Sn + qt * 128 + r) * Hn + c0;
#pragma unroll
    for (int v = 0; v < 4; v++) {
        *(float4*)(Y + v * 4) = make_float4(acc[v*4+0]*inv, acc[v*4+1]*inv,
                                            acc[v*4+2]*inv, acc[v*4+3]*inv);
    }
}

extern "C" void kernel_launch(void* const* d_in, const int* in_sizes, int n_in,
                              void* d_out, int out_size)
{
    const float* x  = (const float*)d_in[0];
    const float* wq = (const float*)d_in[1];
    const float* bq = (const float*)d_in[2];
    const float* wk = (const float*)d_in[3];
    const float* bk = (const float*)d_in[4];
    const float* wv = (const float*)d_in[5];
    const float* bv = (const float*)d_in[6];
    float* y = (float*)d_out;

    conv_w_kernel<<<(3 * Hn * En + 255) / 256, 256>>>(wq, wk, wv);
    qkv_mma_kernel<<<Mn / 64, 128>>>(x, bq, bk, bv);

    cudaFuncSetAttribute(attn_partial_kernel, cudaFuncAttributeMaxDynamicSharedMemorySize, ATT_SMEM);
    attn_partial_kernel<<<dim3(MAXC, QT_N, Bn), 256, ATT_SMEM>>>();

    attn_combine_kernel<<<dim3(2 * QT_N, Bn), 256>>>(y);
}